// round 2
// baseline (speedup 1.0000x reference)
#include <cuda_runtime.h>
#include <math.h>

#define B_  4
#define S_  1024
#define D_  1024
#define H_  16
#define HD_ 64
#define T_  (B_*S_)       // 4096 tokens
#define E_  8
#define F_  4096
#define NSLOT (T_*2)      // 8192 (token, expert) assignments — always exactly 2T

// ---------------- scratch (device globals; no allocation allowed) ----------------
__device__ float g_xn  [T_*D_];
__device__ float g_qh  [T_*D_];
__device__ float g_kh  [T_*D_];
__device__ float g_vh  [T_*D_];
__device__ float g_attn[T_*D_];
__device__ float g_h   [T_*D_];
__device__ float g_hn  [T_*D_];
__device__ float g_H1  [(size_t)NSLOT*F_];   // also holds G = silu(H1)*H3 in-place
__device__ float g_H3  [(size_t)NSLOT*F_];
__device__ float g_Y   [(size_t)NSLOT*D_];
__device__ int   g_topi[T_*2];
__device__ float g_gate[T_*2];
__device__ int   g_counts[E_];
__device__ int   g_offs[E_];
__device__ int   g_cursor[E_];
__device__ int   g_slot_token[NSLOT];
__device__ int   g_token_slot[T_*2];

// ---------------- packed f32x2 helpers (sm_103a FFMA2) ----------------
__device__ __forceinline__ unsigned long long dup2(float a) {
    unsigned long long d;
    asm("mov.b64 %0, {%1, %1};" : "=l"(d) : "f"(a));
    return d;
}
__device__ __forceinline__ void ffma2(unsigned long long& c, unsigned long long a,
                                      unsigned long long b) {
    asm("fma.rn.f32x2 %0, %1, %2, %0;" : "+l"(c) : "l"(a), "l"(b));
}

// ---------------- misc kernels ----------------
__global__ void zero_counts_kernel() {
    if (threadIdx.x < E_) g_counts[threadIdx.x] = 0;
}

__global__ void __launch_bounds__(256)
rmsnorm_kernel(const float* __restrict__ X, const float* __restrict__ W,
               float* __restrict__ Yo) {
    int t = blockIdx.x, tid = threadIdx.x;
    const float4* xp = (const float4*)(X + (size_t)t * D_);
    float4 x = xp[tid];
    float ss = x.x*x.x + x.y*x.y + x.z*x.z + x.w*x.w;
    __shared__ float red[256];
    red[tid] = ss; __syncthreads();
    for (int s = 128; s > 0; s >>= 1) {
        if (tid < s) red[tid] += red[tid + s];
        __syncthreads();
    }
    float inv = rsqrtf(red[0] * (1.0f / 1024.0f) + 1e-6f);
    float4 w = ((const float4*)W)[tid];
    float4 y;
    y.x = x.x*inv*w.x; y.y = x.y*inv*w.y; y.z = x.z*inv*w.z; y.w = x.w*inv*w.w;
    ((float4*)(Yo + (size_t)t * D_))[tid] = y;
}

// ---------------- generic NT GEMM: C[m,n] = sum_k A[m,k] * B[n,k] ----------------
// MOE: per-expert (blockIdx.z), dynamic row count, optional gather of A rows.
template<bool MOE, bool GATHER, bool ADDRES>
__global__ void __launch_bounds__(256, 2)
gemm_nt(const float* __restrict__ A, const float* __restrict__ Bw,
        float* __restrict__ C, const float* __restrict__ Res,
        int M, int N, int K) {
    int m0b, cnt, base = 0;
    const float* Bptr = Bw;
    if (MOE) {
        int e = blockIdx.z;
        cnt = g_counts[e];
        m0b = blockIdx.y * 128;
        if (m0b >= cnt) return;
        base = g_offs[e];
        Bptr = Bw + (size_t)e * N * K;
    } else {
        cnt = M;
        m0b = blockIdx.y * 128;
    }
    int n0b = blockIdx.x * 128;

    __shared__ float As[16][132];   // transposed: As[k][m]
    __shared__ float Bs[16][132];   // transposed: Bs[k][n]

    int tid = threadIdx.x;
    int tx = tid & 15, ty = tid >> 4;
    int m0 = ty * 8, n0 = tx * 8;

    unsigned long long acc[8][4];
    #pragma unroll
    for (int i = 0; i < 8; i++)
        #pragma unroll
        for (int j = 0; j < 4; j++) acc[i][j] = 0ull;

    int lm[2], ln[2], cc4[2];
    const float* aptr[2];
    const float* bptrs[2];
    #pragma unroll
    for (int r = 0; r < 2; r++) {
        int idx = tid + r * 256;
        int mm = idx >> 2, cc = idx & 3;
        cc4[r] = cc * 4;
        int m = m0b + mm;
        int mg;
        if (MOE) {
            int mc = m < cnt ? m : cnt - 1;
            mg = GATHER ? g_slot_token[base + mc] : (base + mc);
        } else {
            mg = m;
        }
        lm[r] = mm;
        aptr[r] = A + (size_t)mg * K + cc * 4;
        ln[r] = mm;
        bptrs[r] = Bptr + (size_t)(n0b + mm) * K + cc * 4;
    }

    for (int kt = 0; kt < K; kt += 16) {
        #pragma unroll
        for (int r = 0; r < 2; r++) {
            float4 v = *(const float4*)(aptr[r] + kt);
            As[cc4[r]+0][lm[r]] = v.x; As[cc4[r]+1][lm[r]] = v.y;
            As[cc4[r]+2][lm[r]] = v.z; As[cc4[r]+3][lm[r]] = v.w;
            float4 w = *(const float4*)(bptrs[r] + kt);
            Bs[cc4[r]+0][ln[r]] = w.x; Bs[cc4[r]+1][ln[r]] = w.y;
            Bs[cc4[r]+2][ln[r]] = w.z; Bs[cc4[r]+3][ln[r]] = w.w;
        }
        __syncthreads();
        #pragma unroll
        for (int k = 0; k < 16; k++) {
            float4 a0 = *(const float4*)&As[k][m0];
            float4 a1 = *(const float4*)&As[k][m0 + 4];
            unsigned long long b0 = *(const unsigned long long*)&Bs[k][n0];
            unsigned long long b1 = *(const unsigned long long*)&Bs[k][n0 + 2];
            unsigned long long b2 = *(const unsigned long long*)&Bs[k][n0 + 4];
            unsigned long long b3 = *(const unsigned long long*)&Bs[k][n0 + 6];
            float av[8] = {a0.x, a0.y, a0.z, a0.w, a1.x, a1.y, a1.z, a1.w};
            #pragma unroll
            for (int i = 0; i < 8; i++) {
                unsigned long long ad = dup2(av[i]);
                ffma2(acc[i][0], ad, b0);
                ffma2(acc[i][1], ad, b1);
                ffma2(acc[i][2], ad, b2);
                ffma2(acc[i][3], ad, b3);
            }
        }
        __syncthreads();
    }

    #pragma unroll
    for (int i = 0; i < 8; i++) {
        int m = m0b + m0 + i;
        if (!MOE || m < cnt) {
            size_t crow = MOE ? (size_t)(base + m) * N : (size_t)m * N;
            float2* cp = (float2*)(C + crow + n0b + n0);
            #pragma unroll
            for (int j = 0; j < 4; j++) {
                float2 v;
                memcpy(&v, &acc[i][j], 8);
                if (ADDRES) {
                    float2 rr = *(const float2*)(Res + crow + n0b + n0 + j * 2);
                    v.x += rr.x; v.y += rr.y;
                }
                cp[j] = v;
            }
        }
    }
}

// ---------------- RoPE (fold 1/sqrt(HD)=0.125 into Q) ----------------
__global__ void rope_kernel(float* __restrict__ qh, float* __restrict__ kh,
                            const float* __restrict__ cosb,
                            const float* __restrict__ sinb) {
    int idx = blockIdx.x * blockDim.x + threadIdx.x;  // T*H*32
    if (idx >= T_ * H_ * 32) return;
    int p = idx & 31;
    int h = (idx >> 5) & (H_ - 1);
    int t = idx >> 9;
    int s = t & (S_ - 1);
    float c = cosb[s * 32 + p], sn = sinb[s * 32 + p];
    size_t off = (size_t)t * D_ + h * HD_ + 2 * p;
    float2 qv = *(float2*)(qh + off);
    float2 kv = *(float2*)(kh + off);
    float2 qo, ko;
    qo.x = (qv.x * c - qv.y * sn) * 0.125f;
    qo.y = (qv.x * sn + qv.y * c) * 0.125f;
    ko.x = kv.x * c - kv.y * sn;
    ko.y = kv.x * sn + kv.y * c;
    *(float2*)(qh + off) = qo;
    *(float2*)(kh + off) = ko;
}

// ---------------- causal attention: one thread per query row ----------------
__global__ void __launch_bounds__(128)
attn_kernel(const float* __restrict__ Q, const float* __restrict__ Kh,
            const float* __restrict__ Vh, float* __restrict__ O) {
    int b = blockIdx.z, h = blockIdx.y, qt = blockIdx.x;
    int tid = threadIdx.x;
    int r = qt * 128 + tid;  // query position in S
    __shared__ float4 Ks[64][16];
    __shared__ float4 Vs[64][16];
    size_t qbase = ((size_t)(b * S_ + r)) * D_ + h * HD_;
    float4 q4[16];
    #pragma unroll
    for (int i = 0; i < 16; i++) q4[i] = *(const float4*)(Q + qbase + i * 4);
    float4 o4[16];
    #pragma unroll
    for (int i = 0; i < 16; i++) o4[i] = make_float4(0.f, 0.f, 0.f, 0.f);
    float mrow = -1e30f, l = 0.f;

    int ntiles = qt * 2 + 2;
    for (int kt = 0; kt < ntiles; kt++) {
        int k0 = kt * 64;
        int j = tid >> 1, half = (tid & 1) * 8;
        size_t kb = ((size_t)(b * S_ + k0 + j)) * D_ + h * HD_ + half * 4;
        #pragma unroll
        for (int i = 0; i < 8; i++) {
            Ks[j][half + i] = *(const float4*)(Kh + kb + i * 4);
            Vs[j][half + i] = *(const float4*)(Vh + kb + i * 4);
        }
        __syncthreads();
        int jmax = r - k0 + 1;
        if (jmax > 64) jmax = 64;
        for (int jj = 0; jj < jmax; jj++) {
            float s0 = 0.f, s1 = 0.f, s2 = 0.f, s3 = 0.f;
            #pragma unroll
            for (int i = 0; i < 16; i += 4) {
                float4 k0v = Ks[jj][i],   k1v = Ks[jj][i+1];
                float4 k2v = Ks[jj][i+2], k3v = Ks[jj][i+3];
                s0 = fmaf(q4[i].x,   k0v.x, fmaf(q4[i].y,   k0v.y, fmaf(q4[i].z,   k0v.z, fmaf(q4[i].w,   k0v.w, s0))));
                s1 = fmaf(q4[i+1].x, k1v.x, fmaf(q4[i+1].y, k1v.y, fmaf(q4[i+1].z, k1v.z, fmaf(q4[i+1].w, k1v.w, s1))));
                s2 = fmaf(q4[i+2].x, k2v.x, fmaf(q4[i+2].y, k2v.y, fmaf(q4[i+2].z, k2v.z, fmaf(q4[i+2].w, k2v.w, s2))));
                s3 = fmaf(q4[i+3].x, k3v.x, fmaf(q4[i+3].y, k3v.y, fmaf(q4[i+3].z, k3v.z, fmaf(q4[i+3].w, k3v.w, s3))));
            }
            float s = (s0 + s1) + (s2 + s3);
            if (s <= mrow) {                       // fast path: max unchanged
                float p = __expf(s - mrow);
                l += p;
                #pragma unroll
                for (int i = 0; i < 16; i++) {
                    float4 vv = Vs[jj][i];
                    o4[i].x = fmaf(p, vv.x, o4[i].x);
                    o4[i].y = fmaf(p, vv.y, o4[i].y);
                    o4[i].z = fmaf(p, vv.z, o4[i].z);
                    o4[i].w = fmaf(p, vv.w, o4[i].w);
                }
            } else {                               // new max: p = 1
                float esc = __expf(mrow - s);
                mrow = s;
                l = fmaf(l, esc, 1.f);
                #pragma unroll
                for (int i = 0; i < 16; i++) {
                    float4 vv = Vs[jj][i];
                    o4[i].x = fmaf(o4[i].x, esc, vv.x);
                    o4[i].y = fmaf(o4[i].y, esc, vv.y);
                    o4[i].z = fmaf(o4[i].z, esc, vv.z);
                    o4[i].w = fmaf(o4[i].w, esc, vv.w);
                }
            }
        }
        __syncthreads();
    }
    float inv = 1.f / l;
    #pragma unroll
    for (int i = 0; i < 16; i++) {
        float4 o = o4[i];
        o.x *= inv; o.y *= inv; o.z *= inv; o.w *= inv;
        *(float4*)(O + qbase + i * 4) = o;
    }
}

// ---------------- router: logits, top-2, gates ----------------
__global__ void __launch_bounds__(256)
router_kernel(const float* __restrict__ Hn, const float* __restrict__ RW,
              const float* __restrict__ RB) {
    int t = blockIdx.x;
    int w = threadIdx.x >> 5, lane = threadIdx.x & 31;
    const float* x = Hn + (size_t)t * D_;
    const float* rw = RW + (size_t)w * D_;
    float acc = 0.f;
    for (int d = lane * 4; d < D_; d += 128) {
        float4 xv = *(const float4*)(x + d);
        float4 wv = *(const float4*)(rw + d);
        acc += xv.x*wv.x + xv.y*wv.y + xv.z*wv.z + xv.w*wv.w;
    }
    #pragma unroll
    for (int o = 16; o; o >>= 1) acc += __shfl_xor_sync(0xffffffffu, acc, o);
    __shared__ float lg[E_];
    if (lane == 0) lg[w] = acc + RB[w];
    __syncthreads();
    if (threadIdx.x == 0) {
        float v0 = -1e30f, v1 = -1e30f; int i0 = 0, i1 = 0;
        #pragma unroll
        for (int e = 0; e < E_; e++) {
            float v = lg[e];
            if (v > v0) { v1 = v0; i1 = i0; v0 = v; i0 = e; }
            else if (v > v1) { v1 = v; i1 = e; }
        }
        float e1 = expf(v1 - v0);
        float inv = 1.f / (1.f + e1);
        g_topi[t*2] = i0; g_topi[t*2+1] = i1;
        g_gate[t*2] = inv; g_gate[t*2+1] = e1 * inv;
        atomicAdd(&g_counts[i0], 1);
        atomicAdd(&g_counts[i1], 1);
    }
}

__global__ void scan_kernel() {
    if (threadIdx.x == 0) {
        int o = 0;
        for (int e = 0; e < E_; e++) { g_offs[e] = o; g_cursor[e] = o; o += g_counts[e]; }
    }
}

__global__ void assign_kernel() {
    int t = blockIdx.x * blockDim.x + threadIdx.x;
    if (t >= T_) return;
    #pragma unroll
    for (int j = 0; j < 2; j++) {
        int e = g_topi[t*2+j];
        int slot = atomicAdd(&g_cursor[e], 1);
        g_slot_token[slot] = t;
        g_token_slot[t*2+j] = slot;
    }
}

__global__ void swiglu_kernel() {
    size_t i = (size_t)blockIdx.x * blockDim.x + threadIdx.x;  // over NSLOT*F/4
    float4 a = ((const float4*)g_H1)[i];
    float4 c = ((const float4*)g_H3)[i];
    a.x = a.x / (1.f + __expf(-a.x)) * c.x;
    a.y = a.y / (1.f + __expf(-a.y)) * c.y;
    a.z = a.z / (1.f + __expf(-a.z)) * c.z;
    a.w = a.w / (1.f + __expf(-a.w)) * c.w;
    ((float4*)g_H1)[i] = a;   // G in-place
}

__global__ void combine_kernel(const float* __restrict__ Hres, float* __restrict__ Out) {
    int i = blockIdx.x * 256 + threadIdx.x;  // over T*D/4
    int t = i >> 8;
    int d4 = i & 255;
    float g0 = g_gate[t*2], g1 = g_gate[t*2+1];
    int s0 = g_token_slot[t*2], s1 = g_token_slot[t*2+1];
    float4 hv = ((const float4*)(Hres + (size_t)t * D_))[d4];
    float4 y0 = ((const float4*)(g_Y + (size_t)s0 * D_))[d4];
    float4 y1 = ((const float4*)(g_Y + (size_t)s1 * D_))[d4];
    float4 o;
    o.x = hv.x + g0*y0.x + g1*y1.x;
    o.y = hv.y + g0*y0.y + g1*y1.y;
    o.z = hv.z + g0*y0.z + g1*y1.z;
    o.w = hv.w + g0*y0.w + g1*y1.w;
    ((float4*)Out)[i] = o;
}

// ---------------- host ----------------
extern "C" void kernel_launch(void* const* d_in, const int* in_sizes, int n_in,
                              void* d_out, int out_size) {
    const float* q    = (const float*)d_in[0];
    // d_in[1] (k), d_in[2] (v) are unused by the reference (qn passed for all three)
    const float* fcos = (const float*)d_in[3];
    const float* fsin = (const float*)d_in[4];
    const float* attw = (const float*)d_in[5];
    const float* ffnw = (const float*)d_in[6];
    const float* wq   = (const float*)d_in[7];
    const float* wk   = (const float*)d_in[8];
    const float* wv   = (const float*)d_in[9];
    const float* wo   = (const float*)d_in[10];
    const float* rw   = (const float*)d_in[11];
    const float* rb   = (const float*)d_in[12];
    const float* w1   = (const float*)d_in[13];
    const float* w2   = (const float*)d_in[14];
    const float* w3   = (const float*)d_in[15];
    float* out = (float*)d_out;

    float *xn, *qh, *kh, *vh, *attn, *hbuf, *hn, *H1, *H3, *Y;
    cudaGetSymbolAddress((void**)&xn,   g_xn);
    cudaGetSymbolAddress((void**)&qh,   g_qh);
    cudaGetSymbolAddress((void**)&kh,   g_kh);
    cudaGetSymbolAddress((void**)&vh,   g_vh);
    cudaGetSymbolAddress((void**)&attn, g_attn);
    cudaGetSymbolAddress((void**)&hbuf, g_h);
    cudaGetSymbolAddress((void**)&hn,   g_hn);
    cudaGetSymbolAddress((void**)&H1,   g_H1);
    cudaGetSymbolAddress((void**)&H3,   g_H3);
    cudaGetSymbolAddress((void**)&Y,    g_Y);

    zero_counts_kernel<<<1, 32>>>();
    rmsnorm_kernel<<<T_, 256>>>(q, attw, xn);

    dim3 gq(D_ / 128, T_ / 128);
    gemm_nt<false, false, false><<<gq, 256>>>(xn, wq, qh, nullptr, T_, D_, D_);
    gemm_nt<false, false, false><<<gq, 256>>>(xn, wk, kh, nullptr, T_, D_, D_);
    gemm_nt<false, false, false><<<gq, 256>>>(xn, wv, vh, nullptr, T_, D_, D_);

    rope_kernel<<<(T_ * H_ * 32 + 255) / 256, 256>>>(qh, kh, fcos, fsin);
    attn_kernel<<<dim3(S_ / 128, H_, B_), 128>>>(qh, kh, vh, attn);
    gemm_nt<false, false, true><<<gq, 256>>>(attn, wo, hbuf, q, T_, D_, D_);

    rmsnorm_kernel<<<T_, 256>>>(hbuf, ffnw, hn);
    router_kernel<<<T_, 256>>>(hn, rw, rb);
    scan_kernel<<<1, 1>>>();
    assign_kernel<<<T_ / 256, 256>>>();

    gemm_nt<true, true, false><<<dim3(F_ / 128, NSLOT / 128, E_), 256>>>(hn, w1, H1, nullptr, 0, F_, D_);
    gemm_nt<true, true, false><<<dim3(F_ / 128, NSLOT / 128, E_), 256>>>(hn, w3, H3, nullptr, 0, F_, D_);
    swiglu_kernel<<<(int)((size_t)NSLOT * F_ / 4 / 256), 256>>>();
    gemm_nt<true, false, false><<<dim3(D_ / 128, NSLOT / 128, E_), 256>>>(H1, w2, Y, nullptr, 0, D_, F_);

    combine_kernel<<<T_ * D_ / 4 / 256, 256>>>(hbuf, out);
}

// round 4
// speedup vs baseline: 1.9750x; 1.9750x over previous
#include <cuda_runtime.h>
#include <math.h>
#include <stdint.h>

#define B_  4
#define S_  1024
#define D_  1024
#define H_  16
#define HD_ 64
#define T_  (B_*S_)
#define E_  8
#define F_  4096
#define NSLOT (T_*2)
#define NPAD  (NSLOT+128)

// ---------------- scratch ----------------
__device__ float g_xn  [T_*D_];
__device__ float g_qh  [T_*D_];
__device__ float g_kh  [T_*D_];
__device__ float g_vh  [T_*D_];
__device__ float g_attn[T_*D_];
__device__ float g_h   [T_*D_];
__device__ float g_hn  [T_*D_];
__device__ float g_Ag  [(size_t)NPAD*D_];    // gathered + tf32-rounded activations
__device__ float g_H1  [(size_t)NPAD*F_];    // H1, then G=tf32(silu(H1)*H3) in place
__device__ float g_H3  [(size_t)NSLOT*F_];
__device__ float g_Y   [(size_t)NSLOT*D_];
__device__ float g_w1r [(size_t)E_*F_*D_];
__device__ float g_w2r [(size_t)E_*D_*F_];
__device__ float g_w3r [(size_t)E_*F_*D_];
__device__ int   g_topi[T_*2];
__device__ float g_gate[T_*2];
__device__ int   g_counts[E_];
__device__ int   g_offs[E_];
__device__ int   g_cursor[E_];
__device__ int   g_slot_token[NSLOT];
__device__ int   g_token_slot[T_*2];

// ---------------- helpers ----------------
__device__ __forceinline__ unsigned long long dup2(float a) {
    unsigned long long d;
    asm("mov.b64 %0, {%1, %1};" : "=l"(d) : "f"(a));
    return d;
}
__device__ __forceinline__ void ffma2(unsigned long long& c, unsigned long long a,
                                      unsigned long long b) {
    asm("fma.rn.f32x2 %0, %1, %2, %0;" : "+l"(c) : "l"(a), "l"(b));
}
__device__ __forceinline__ float tf32r(float x) {
    uint32_t u;
    asm("cvt.rna.tf32.f32 %0, %1;" : "=r"(u) : "f"(x));
    return __uint_as_float(u);
}
__device__ __forceinline__ void cp16(uint32_t s, const void* g) {
    asm volatile("cp.async.cg.shared.global [%0], [%1], 16;" :: "r"(s), "l"(g));
}
__device__ __forceinline__ uint32_t smem_u32(const void* p) {
    uint32_t a;
    asm("{ .reg .u64 t; cvta.to.shared.u64 t, %1; cvt.u32.u64 %0, t; }" : "=r"(a) : "l"(p));
    return a;
}
#define CP_COMMIT() asm volatile("cp.async.commit_group;" ::: "memory")
#define CP_WAIT1()  asm volatile("cp.async.wait_group 1;" ::: "memory")

__device__ __forceinline__ void mma_tf32(float& c0, float& c1, float& c2, float& c3,
                                         uint32_t a0, uint32_t a1, uint32_t a2, uint32_t a3,
                                         uint32_t b0, uint32_t b1) {
    asm volatile("mma.sync.aligned.m16n8k8.row.col.f32.tf32.tf32.f32 "
                 "{%0,%1,%2,%3}, {%4,%5,%6,%7}, {%8,%9}, {%0,%1,%2,%3};"
                 : "+f"(c0), "+f"(c1), "+f"(c2), "+f"(c3)
                 : "r"(a0), "r"(a1), "r"(a2), "r"(a3), "r"(b0), "r"(b1));
}

// ---------------- small kernels ----------------
__global__ void zero_counts_kernel() { if (threadIdx.x < E_) g_counts[threadIdx.x] = 0; }

__global__ void __launch_bounds__(256)
rmsnorm_kernel(const float* __restrict__ X, const float* __restrict__ W, float* __restrict__ Yo) {
    int t = blockIdx.x, tid = threadIdx.x;
    float4 x = ((const float4*)(X + (size_t)t * D_))[tid];
    float ss = x.x*x.x + x.y*x.y + x.z*x.z + x.w*x.w;
    __shared__ float red[256];
    red[tid] = ss; __syncthreads();
    for (int s = 128; s > 0; s >>= 1) { if (tid < s) red[tid] += red[tid + s]; __syncthreads(); }
    float inv = rsqrtf(red[0] * (1.0f / 1024.0f) + 1e-6f);
    float4 w = ((const float4*)W)[tid];
    float4 y;
    y.x = x.x*inv*w.x; y.y = x.y*inv*w.y; y.z = x.z*inv*w.z; y.w = x.w*inv*w.w;
    ((float4*)(Yo + (size_t)t * D_))[tid] = y;
}

__global__ void __launch_bounds__(256)
round_copy_kernel(const float* __restrict__ src, float* __restrict__ dst) {
    size_t i = (size_t)blockIdx.x * 256 + threadIdx.x;
    float4 v = ((const float4*)src)[i];
    v.x = tf32r(v.x); v.y = tf32r(v.y); v.z = tf32r(v.z); v.w = tf32r(v.w);
    ((float4*)dst)[i] = v;
}

__global__ void __launch_bounds__(256)
gather_round_kernel(const float* __restrict__ Hn) {
    int i = blockIdx.x * 256 + threadIdx.x;   // over NSLOT * D/4
    int slot = i >> 8, d4 = i & 255;
    int t = g_slot_token[slot];
    float4 v = ((const float4*)(Hn + (size_t)t * D_))[d4];
    v.x = tf32r(v.x); v.y = tf32r(v.y); v.z = tf32r(v.z); v.w = tf32r(v.w);
    ((float4*)(g_Ag + (size_t)slot * D_))[d4] = v;
}

// ---------------- dense fp32 FFMA2 GEMM (router-critical path; unchanged) ----------------
template<bool ADDRES>
__global__ void __launch_bounds__(256, 2)
gemm_nt(const float* __restrict__ A, const float* __restrict__ Bw,
        float* __restrict__ C, const float* __restrict__ Res, int K) {
    int m0b = blockIdx.y * 128, n0b = blockIdx.x * 128;
    __shared__ float As[16][132];
    __shared__ float Bs[16][132];
    int tid = threadIdx.x;
    int tx = tid & 15, ty = tid >> 4;
    int m0 = ty * 8, n0 = tx * 8;
    unsigned long long acc[8][4];
    #pragma unroll
    for (int i = 0; i < 8; i++)
        #pragma unroll
        for (int j = 0; j < 4; j++) acc[i][j] = 0ull;
    int lm[2], cc4[2];
    const float* aptr[2];
    const float* bptrs[2];
    #pragma unroll
    for (int r = 0; r < 2; r++) {
        int idx = tid + r * 256;
        int mm = idx >> 2, cc = idx & 3;
        cc4[r] = cc * 4; lm[r] = mm;
        aptr[r]  = A  + (size_t)(m0b + mm) * K + cc * 4;
        bptrs[r] = Bw + (size_t)(n0b + mm) * K + cc * 4;
    }
    for (int kt = 0; kt < K; kt += 16) {
        #pragma unroll
        for (int r = 0; r < 2; r++) {
            float4 v = *(const float4*)(aptr[r] + kt);
            As[cc4[r]+0][lm[r]] = v.x; As[cc4[r]+1][lm[r]] = v.y;
            As[cc4[r]+2][lm[r]] = v.z; As[cc4[r]+3][lm[r]] = v.w;
            float4 w = *(const float4*)(bptrs[r] + kt);
            Bs[cc4[r]+0][lm[r]] = w.x; Bs[cc4[r]+1][lm[r]] = w.y;
            Bs[cc4[r]+2][lm[r]] = w.z; Bs[cc4[r]+3][lm[r]] = w.w;
        }
        __syncthreads();
        #pragma unroll
        for (int k = 0; k < 16; k++) {
            float4 a0 = *(const float4*)&As[k][m0];
            float4 a1 = *(const float4*)&As[k][m0 + 4];
            unsigned long long b0 = *(const unsigned long long*)&Bs[k][n0];
            unsigned long long b1 = *(const unsigned long long*)&Bs[k][n0 + 2];
            unsigned long long b2 = *(const unsigned long long*)&Bs[k][n0 + 4];
            unsigned long long b3 = *(const unsigned long long*)&Bs[k][n0 + 6];
            float av[8] = {a0.x, a0.y, a0.z, a0.w, a1.x, a1.y, a1.z, a1.w};
            #pragma unroll
            for (int i = 0; i < 8; i++) {
                unsigned long long ad = dup2(av[i]);
                ffma2(acc[i][0], ad, b0); ffma2(acc[i][1], ad, b1);
                ffma2(acc[i][2], ad, b2); ffma2(acc[i][3], ad, b3);
            }
        }
        __syncthreads();
    }
    #pragma unroll
    for (int i = 0; i < 8; i++) {
        size_t crow = (size_t)(m0b + m0 + i) * D_;
        float2* cp = (float2*)(C + crow + n0b + n0);
        #pragma unroll
        for (int j = 0; j < 4; j++) {
            float2 v; memcpy(&v, &acc[i][j], 8);
            if (ADDRES) {
                float2 rr = *(const float2*)(Res + crow + n0b + n0 + j * 2);
                v.x += rr.x; v.y += rr.y;
            }
            cp[j] = v;
        }
    }
}

// ---------------- RoPE ----------------
__global__ void rope_kernel(float* __restrict__ qh, float* __restrict__ kh,
                            const float* __restrict__ cosb, const float* __restrict__ sinb) {
    int idx = blockIdx.x * blockDim.x + threadIdx.x;
    if (idx >= T_ * H_ * 32) return;
    int p = idx & 31, h = (idx >> 5) & (H_ - 1), t = idx >> 9, s = t & (S_ - 1);
    float c = cosb[s * 32 + p], sn = sinb[s * 32 + p];
    size_t off = (size_t)t * D_ + h * HD_ + 2 * p;
    float2 qv = *(float2*)(qh + off);
    float2 kv = *(float2*)(kh + off);
    float2 qo, ko;
    qo.x = (qv.x * c - qv.y * sn) * 0.125f;
    qo.y = (qv.x * sn + qv.y * c) * 0.125f;
    ko.x = kv.x * c - kv.y * sn;
    ko.y = kv.x * sn + kv.y * c;
    *(float2*)(qh + off) = qo;
    *(float2*)(kh + off) = ko;
}

// ---------------- attention (unchanged) ----------------
__global__ void __launch_bounds__(128)
attn_kernel(const float* __restrict__ Q, const float* __restrict__ Kh,
            const float* __restrict__ Vh, float* __restrict__ O) {
    int b = blockIdx.z, h = blockIdx.y, qt = blockIdx.x;
    int tid = threadIdx.x;
    int r = qt * 128 + tid;
    __shared__ float4 Ks[64][16];
    __shared__ float4 Vs[64][16];
    size_t qbase = ((size_t)(b * S_ + r)) * D_ + h * HD_;
    float4 q4[16];
    #pragma unroll
    for (int i = 0; i < 16; i++) q4[i] = *(const float4*)(Q + qbase + i * 4);
    float4 o4[16];
    #pragma unroll
    for (int i = 0; i < 16; i++) o4[i] = make_float4(0.f, 0.f, 0.f, 0.f);
    float mrow = -1e30f, l = 0.f;
    int ntiles = qt * 2 + 2;
    for (int kt = 0; kt < ntiles; kt++) {
        int k0 = kt * 64;
        int j = tid >> 1, half = (tid & 1) * 8;
        size_t kb = ((size_t)(b * S_ + k0 + j)) * D_ + h * HD_ + half * 4;
        #pragma unroll
        for (int i = 0; i < 8; i++) {
            Ks[j][half + i] = *(const float4*)(Kh + kb + i * 4);
            Vs[j][half + i] = *(const float4*)(Vh + kb + i * 4);
        }
        __syncthreads();
        int jmax = r - k0 + 1;
        if (jmax > 64) jmax = 64;
        for (int jj = 0; jj < jmax; jj++) {
            float s0 = 0.f, s1 = 0.f, s2 = 0.f, s3 = 0.f;
            #pragma unroll
            for (int i = 0; i < 16; i += 4) {
                float4 k0v = Ks[jj][i],   k1v = Ks[jj][i+1];
                float4 k2v = Ks[jj][i+2], k3v = Ks[jj][i+3];
                s0 = fmaf(q4[i].x,   k0v.x, fmaf(q4[i].y,   k0v.y, fmaf(q4[i].z,   k0v.z, fmaf(q4[i].w,   k0v.w, s0))));
                s1 = fmaf(q4[i+1].x, k1v.x, fmaf(q4[i+1].y, k1v.y, fmaf(q4[i+1].z, k1v.z, fmaf(q4[i+1].w, k1v.w, s1))));
                s2 = fmaf(q4[i+2].x, k2v.x, fmaf(q4[i+2].y, k2v.y, fmaf(q4[i+2].z, k2v.z, fmaf(q4[i+2].w, k2v.w, s2))));
                s3 = fmaf(q4[i+3].x, k3v.x, fmaf(q4[i+3].y, k3v.y, fmaf(q4[i+3].z, k3v.z, fmaf(q4[i+3].w, k3v.w, s3))));
            }
            float s = (s0 + s1) + (s2 + s3);
            if (s <= mrow) {
                float p = __expf(s - mrow);
                l += p;
                #pragma unroll
                for (int i = 0; i < 16; i++) {
                    float4 vv = Vs[jj][i];
                    o4[i].x = fmaf(p, vv.x, o4[i].x); o4[i].y = fmaf(p, vv.y, o4[i].y);
                    o4[i].z = fmaf(p, vv.z, o4[i].z); o4[i].w = fmaf(p, vv.w, o4[i].w);
                }
            } else {
                float esc = __expf(mrow - s);
                mrow = s;
                l = fmaf(l, esc, 1.f);
                #pragma unroll
                for (int i = 0; i < 16; i++) {
                    float4 vv = Vs[jj][i];
                    o4[i].x = fmaf(o4[i].x, esc, vv.x); o4[i].y = fmaf(o4[i].y, esc, vv.y);
                    o4[i].z = fmaf(o4[i].z, esc, vv.z); o4[i].w = fmaf(o4[i].w, esc, vv.w);
                }
            }
        }
        __syncthreads();
    }
    float inv = 1.f / l;
    #pragma unroll
    for (int i = 0; i < 16; i++) {
        float4 o = o4[i];
        o.x *= inv; o.y *= inv; o.z *= inv; o.w *= inv;
        *(float4*)(O + qbase + i * 4) = o;
    }
}

// ---------------- router / scan / assign (unchanged) ----------------
__global__ void __launch_bounds__(256)
router_kernel(const float* __restrict__ Hn, const float* __restrict__ RW,
              const float* __restrict__ RB) {
    int t = blockIdx.x;
    int w = threadIdx.x >> 5, lane = threadIdx.x & 31;
    const float* x = Hn + (size_t)t * D_;
    const float* rw = RW + (size_t)w * D_;
    float acc = 0.f;
    for (int d = lane * 4; d < D_; d += 128) {
        float4 xv = *(const float4*)(x + d);
        float4 wv = *(const float4*)(rw + d);
        acc += xv.x*wv.x + xv.y*wv.y + xv.z*wv.z + xv.w*wv.w;
    }
    #pragma unroll
    for (int o = 16; o; o >>= 1) acc += __shfl_xor_sync(0xffffffffu, acc, o);
    __shared__ float lg[E_];
    if (lane == 0) lg[w] = acc + RB[w];
    __syncthreads();
    if (threadIdx.x == 0) {
        float v0 = -1e30f, v1 = -1e30f; int i0 = 0, i1 = 0;
        #pragma unroll
        for (int e = 0; e < E_; e++) {
            float v = lg[e];
            if (v > v0) { v1 = v0; i1 = i0; v0 = v; i0 = e; }
            else if (v > v1) { v1 = v; i1 = e; }
        }
        float e1 = expf(v1 - v0);
        float inv = 1.f / (1.f + e1);
        g_topi[t*2] = i0; g_topi[t*2+1] = i1;
        g_gate[t*2] = inv; g_gate[t*2+1] = e1 * inv;
        atomicAdd(&g_counts[i0], 1);
        atomicAdd(&g_counts[i1], 1);
    }
}

__global__ void scan_kernel() {
    if (threadIdx.x == 0) {
        int o = 0;
        for (int e = 0; e < E_; e++) { g_offs[e] = o; g_cursor[e] = o; o += g_counts[e]; }
    }
}

__global__ void assign_kernel() {
    int t = blockIdx.x * blockDim.x + threadIdx.x;
    if (t >= T_) return;
    #pragma unroll
    for (int j = 0; j < 2; j++) {
        int e = g_topi[t*2+j];
        int slot = atomicAdd(&g_cursor[e], 1);
        g_slot_token[slot] = t;
        g_token_slot[t*2+j] = slot;
    }
}

// ================= MoE GEMM via mma.sync tf32 (compute_103-legal) =================
// C[base+m, n] = sum_k A[base+m0b+m, k] * B[e*N*K + n, k]   (both operands NT, tf32-prerounded)
// CTA tile 128x128, warp grid 2(m) x 4(n), warp tile 64x32 of m16n8k8 frags.
// K-chunk 64, 3-stage cp.async. SMEM row stride 68 floats (272B) -> conflict-free frag LDS.
#define KC 64
#define STRD 68
#define OPBYTES (128*STRD*4)          // 34816 per operand per stage
#define STAGE_B (2*OPBYTES)           // 69632
#define TC_SMEM (3*STAGE_B)           // 208896

__global__ void __launch_bounds__(256, 1)
moe_gemm_tc(const float* __restrict__ A, const float* __restrict__ Bw,
            float* __restrict__ C, int K, int N) {
    int e = blockIdx.z;
    int cnt = g_counts[e];
    int m0b = blockIdx.y * 128;
    if (m0b >= cnt) return;
    int base = g_offs[e];
    int n0b = blockIdx.x * 128;
    const float* Arow = A  + (size_t)(base + m0b) * K;
    const float* Brow = Bw + (size_t)e * N * K + (size_t)n0b * K;

    extern __shared__ float smf[];
    uint32_t sm0 = smem_u32(smf);

    int tid = threadIdx.x;
    int wid = tid >> 5, lane = tid & 31;
    int wm = wid >> 2, wn = wid & 3;           // warp grid 2x4
    int g = lane >> 2, qd = lane & 3;          // mma group / quad

    float c[4][4][4];
    #pragma unroll
    for (int mi = 0; mi < 4; mi++)
        #pragma unroll
        for (int ni = 0; ni < 4; ni++)
            #pragma unroll
            for (int r = 0; r < 4; r++) c[mi][ni][r] = 0.f;

    const int NC = K / KC;

    // per-thread load slots: 8 x 16B per operand per stage
    int lrow[8], lseg[8];
    #pragma unroll
    for (int j = 0; j < 8; j++) {
        int idx = tid + j * 256;               // 0..2047
        lrow[j] = idx >> 4;
        lseg[j] = idx & 15;
    }

    // prologue: chunks 0,1 -> stages 0,1
    #pragma unroll
    for (int pc = 0; pc < 2; pc++) {
        uint32_t sa = sm0 + pc * STAGE_B;
        uint32_t sb = sa + OPBYTES;
        #pragma unroll
        for (int j = 0; j < 8; j++) {
            uint32_t d = lrow[j] * (STRD * 4) + lseg[j] * 16;
            size_t go = (size_t)lrow[j] * K + pc * KC + lseg[j] * 4;
            cp16(sa + d, Arow + go);
            cp16(sb + d, Brow + go);
        }
        CP_COMMIT();
    }

    for (int cix = 0; cix < NC; cix++) {
        int sc = cix % 3;
        CP_WAIT1();
        __syncthreads();
        if (cix + 2 < NC) {
            int st = (cix + 2) % 3;
            uint32_t sa = sm0 + st * STAGE_B;
            uint32_t sb = sa + OPBYTES;
            #pragma unroll
            for (int j = 0; j < 8; j++) {
                uint32_t d = lrow[j] * (STRD * 4) + lseg[j] * 16;
                size_t go = (size_t)lrow[j] * K + (cix + 2) * KC + lseg[j] * 4;
                cp16(sa + d, Arow + go);
                cp16(sb + d, Brow + go);
            }
        }
        CP_COMMIT();

        const float* As = smf + sc * (STAGE_B / 4);
        const float* Bs = As + (OPBYTES / 4);
        const float* Aw = As + (wm * 64) * STRD;
        const float* Bn = Bs + (wn * 32) * STRD;

        #pragma unroll
        for (int ks = 0; ks < KC / 8; ks++) {
            int k0 = ks * 8;
            uint32_t a[4][4];
            #pragma unroll
            for (int mi = 0; mi < 4; mi++) {
                const float* ap = Aw + (mi * 16 + g) * STRD + k0 + qd;
                a[mi][0] = __float_as_uint(ap[0]);
                a[mi][1] = __float_as_uint(ap[8 * STRD]);
                a[mi][2] = __float_as_uint(ap[4]);
                a[mi][3] = __float_as_uint(ap[8 * STRD + 4]);
            }
            uint32_t b[4][2];
            #pragma unroll
            for (int ni = 0; ni < 4; ni++) {
                const float* bp = Bn + (ni * 8 + g) * STRD + k0 + qd;
                b[ni][0] = __float_as_uint(bp[0]);
                b[ni][1] = __float_as_uint(bp[4]);
            }
            #pragma unroll
            for (int mi = 0; mi < 4; mi++)
                #pragma unroll
                for (int ni = 0; ni < 4; ni++)
                    mma_tf32(c[mi][ni][0], c[mi][ni][1], c[mi][ni][2], c[mi][ni][3],
                             a[mi][0], a[mi][1], a[mi][2], a[mi][3],
                             b[ni][0], b[ni][1]);
        }
        __syncthreads();
    }

    // epilogue: c0,c1 -> (row, col..col+1); c2,c3 -> (row+8, ...)
    #pragma unroll
    for (int mi = 0; mi < 4; mi++) {
        int mr0 = m0b + wm * 64 + mi * 16 + g;
        #pragma unroll
        for (int ni = 0; ni < 4; ni++) {
            int col = n0b + wn * 32 + ni * 8 + qd * 2;
            if (mr0 < cnt) {
                float2 v; v.x = c[mi][ni][0]; v.y = c[mi][ni][1];
                *(float2*)(C + (size_t)(base + mr0) * N + col) = v;
            }
            if (mr0 + 8 < cnt) {
                float2 v; v.x = c[mi][ni][2]; v.y = c[mi][ni][3];
                *(float2*)(C + (size_t)(base + mr0 + 8) * N + col) = v;
            }
        }
    }
}

// ---------------- swiglu (+tf32 round for w2 input), G written into g_H1 ----------------
__global__ void swiglu_kernel() {
    size_t i = (size_t)blockIdx.x * 256 + threadIdx.x;  // over NSLOT*F/4
    float4 a = ((const float4*)g_H1)[i];
    float4 cc = ((const float4*)g_H3)[i];
    a.x = tf32r(a.x / (1.f + __expf(-a.x)) * cc.x);
    a.y = tf32r(a.y / (1.f + __expf(-a.y)) * cc.y);
    a.z = tf32r(a.z / (1.f + __expf(-a.z)) * cc.z);
    a.w = tf32r(a.w / (1.f + __expf(-a.w)) * cc.w);
    ((float4*)g_H1)[i] = a;
}

// ---------------- combine ----------------
__global__ void combine_kernel(const float* __restrict__ Hres, float* __restrict__ Out) {
    int i = blockIdx.x * 256 + threadIdx.x;
    int t = i >> 8, d4 = i & 255;
    float g0 = g_gate[t*2], g1 = g_gate[t*2+1];
    int s0 = g_token_slot[t*2], s1 = g_token_slot[t*2+1];
    float4 hv = ((const float4*)(Hres + (size_t)t * D_))[d4];
    float4 y0 = ((const float4*)(g_Y + (size_t)s0 * D_))[d4];
    float4 y1 = ((const float4*)(g_Y + (size_t)s1 * D_))[d4];
    float4 o;
    o.x = hv.x + g0*y0.x + g1*y1.x;
    o.y = hv.y + g0*y0.y + g1*y1.y;
    o.z = hv.z + g0*y0.z + g1*y1.z;
    o.w = hv.w + g0*y0.w + g1*y1.w;
    ((float4*)Out)[i] = o;
}

// ---------------- host ----------------
extern "C" void kernel_launch(void* const* d_in, const int* in_sizes, int n_in,
                              void* d_out, int out_size) {
    const float* q    = (const float*)d_in[0];
    const float* fcos = (const float*)d_in[3];
    const float* fsin = (const float*)d_in[4];
    const float* attw = (const float*)d_in[5];
    const float* ffnw = (const float*)d_in[6];
    const float* wq   = (const float*)d_in[7];
    const float* wk   = (const float*)d_in[8];
    const float* wv   = (const float*)d_in[9];
    const float* wo   = (const float*)d_in[10];
    const float* rw   = (const float*)d_in[11];
    const float* rb   = (const float*)d_in[12];
    const float* w1   = (const float*)d_in[13];
    const float* w2   = (const float*)d_in[14];
    const float* w3   = (const float*)d_in[15];
    float* out = (float*)d_out;

    float *xn, *qh, *kh, *vh, *attn, *hbuf, *hn, *Ag, *H1, *H3, *Y, *w1r, *w2r, *w3r;
    cudaGetSymbolAddress((void**)&xn,   g_xn);
    cudaGetSymbolAddress((void**)&qh,   g_qh);
    cudaGetSymbolAddress((void**)&kh,   g_kh);
    cudaGetSymbolAddress((void**)&vh,   g_vh);
    cudaGetSymbolAddress((void**)&attn, g_attn);
    cudaGetSymbolAddress((void**)&hbuf, g_h);
    cudaGetSymbolAddress((void**)&hn,   g_hn);
    cudaGetSymbolAddress((void**)&Ag,   g_Ag);
    cudaGetSymbolAddress((void**)&H1,   g_H1);
    cudaGetSymbolAddress((void**)&H3,   g_H3);
    cudaGetSymbolAddress((void**)&Y,    g_Y);
    cudaGetSymbolAddress((void**)&w1r,  g_w1r);
    cudaGetSymbolAddress((void**)&w2r,  g_w2r);
    cudaGetSymbolAddress((void**)&w3r,  g_w3r);

    cudaFuncSetAttribute(moe_gemm_tc, cudaFuncAttributeMaxDynamicSharedMemorySize, TC_SMEM);

    const int WN4 = (int)((size_t)E_ * F_ * D_ / 4);
    round_copy_kernel<<<WN4 / 256, 256>>>(w1, w1r);
    round_copy_kernel<<<WN4 / 256, 256>>>(w2, w2r);
    round_copy_kernel<<<WN4 / 256, 256>>>(w3, w3r);

    zero_counts_kernel<<<1, 32>>>();
    rmsnorm_kernel<<<T_, 256>>>(q, attw, xn);

    dim3 gq(D_ / 128, T_ / 128);
    gemm_nt<false><<<gq, 256>>>(xn, wq, qh, nullptr, D_);
    gemm_nt<false><<<gq, 256>>>(xn, wk, kh, nullptr, D_);
    gemm_nt<false><<<gq, 256>>>(xn, wv, vh, nullptr, D_);

    rope_kernel<<<(T_ * H_ * 32 + 255) / 256, 256>>>(qh, kh, fcos, fsin);
    attn_kernel<<<dim3(S_ / 128, H_, B_), 128>>>(qh, kh, vh, attn);
    gemm_nt<true><<<gq, 256>>>(attn, wo, hbuf, q, D_);

    rmsnorm_kernel<<<T_, 256>>>(hbuf, ffnw, hn);
    router_kernel<<<T_, 256>>>(hn, rw, rb);
    scan_kernel<<<1, 1>>>();
    assign_kernel<<<T_ / 256, 256>>>();
    gather_round_kernel<<<NSLOT * (D_ / 4) / 256, 256>>>(hn);

    moe_gemm_tc<<<dim3(F_ / 128, NSLOT / 128, E_), 256, TC_SMEM>>>(Ag, w1r, H1, D_, F_);
    moe_gemm_tc<<<dim3(F_ / 128, NSLOT / 128, E_), 256, TC_SMEM>>>(Ag, w3r, H3, D_, F_);
    swiglu_kernel<<<(int)((size_t)NSLOT * F_ / 4 / 256), 256>>>();
    moe_gemm_tc<<<dim3(D_ / 128, NSLOT / 128, E_), 256, TC_SMEM>>>(H1, w2r, Y, F_, D_);

    combine_kernel<<<T_ * D_ / 4 / 256, 256>>>(hbuf, out);
}

// round 6
// speedup vs baseline: 2.1033x; 1.0650x over previous
#include <cuda_runtime.h>
#include <math.h>
#include <stdint.h>

#define B_  4
#define S_  1024
#define D_  1024
#define H_  16
#define HD_ 64
#define T_  (B_*S_)
#define E_  8
#define F_  4096
#define NSLOT (T_*2)
#define NPAD  (NSLOT+128)

// ---------------- scratch ----------------
__device__ float g_xn  [T_*D_];
__device__ float g_qh  [T_*D_];
__device__ float g_kh  [T_*D_];
__device__ float g_vh  [T_*D_];
__device__ float g_attn[T_*D_];
__device__ float g_h   [T_*D_];
__device__ float g_hn  [T_*D_];
__device__ float g_Ag  [(size_t)NPAD*D_];    // gathered + tf32-rounded activations
__device__ float g_G   [(size_t)NPAD*F_];    // G = tf32(silu(H1)*H3), fused epilogue
__device__ float g_Y   [(size_t)NSLOT*D_];
__device__ float g_w1r [(size_t)E_*F_*D_];
__device__ float g_w2r [(size_t)E_*D_*F_];
__device__ float g_w3r [(size_t)E_*F_*D_];
__device__ int   g_topi[T_*2];
__device__ float g_gate[T_*2];
__device__ int   g_counts[E_];
__device__ int   g_offs[E_];
__device__ int   g_cursor[E_];
__device__ int   g_slot_token[NSLOT];
__device__ int   g_token_slot[T_*2];

// ---------------- helpers ----------------
__device__ __forceinline__ unsigned long long dup2(float a) {
    unsigned long long d;
    asm("mov.b64 %0, {%1, %1};" : "=l"(d) : "f"(a));
    return d;
}
__device__ __forceinline__ void ffma2(unsigned long long& c, unsigned long long a,
                                      unsigned long long b) {
    asm("fma.rn.f32x2 %0, %1, %2, %0;" : "+l"(c) : "l"(a), "l"(b));
}
__device__ __forceinline__ float tf32r(float x) {
    uint32_t u;
    asm("cvt.rna.tf32.f32 %0, %1;" : "=r"(u) : "f"(x));
    return __uint_as_float(u);
}
__device__ __forceinline__ void cp16(uint32_t s, const void* g) {
    asm volatile("cp.async.cg.shared.global [%0], [%1], 16;" :: "r"(s), "l"(g));
}
__device__ __forceinline__ uint32_t smem_u32(const void* p) {
    uint32_t a;
    asm("{ .reg .u64 t; cvta.to.shared.u64 t, %1; cvt.u32.u64 %0, t; }" : "=r"(a) : "l"(p));
    return a;
}
#define CP_COMMIT() asm volatile("cp.async.commit_group;" ::: "memory")
#define CP_WAIT0()  asm volatile("cp.async.wait_group 0;" ::: "memory")
#define CP_WAIT1()  asm volatile("cp.async.wait_group 1;" ::: "memory")

__device__ __forceinline__ void mma_tf32(float& c0, float& c1, float& c2, float& c3,
                                         uint32_t a0, uint32_t a1, uint32_t a2, uint32_t a3,
                                         uint32_t b0, uint32_t b1) {
    asm volatile("mma.sync.aligned.m16n8k8.row.col.f32.tf32.tf32.f32 "
                 "{%0,%1,%2,%3}, {%4,%5,%6,%7}, {%8,%9}, {%0,%1,%2,%3};"
                 : "+f"(c0), "+f"(c1), "+f"(c2), "+f"(c3)
                 : "r"(a0), "r"(a1), "r"(a2), "r"(a3), "r"(b0), "r"(b1));
}
__device__ __forceinline__ void ldsm4(uint32_t& r0, uint32_t& r1, uint32_t& r2, uint32_t& r3,
                                      uint32_t addr) {
    asm volatile("ldmatrix.sync.aligned.m8n8.x4.shared.b16 {%0,%1,%2,%3}, [%4];"
                 : "=r"(r0), "=r"(r1), "=r"(r2), "=r"(r3) : "r"(addr));
}
__device__ __forceinline__ void ldsm2(uint32_t& r0, uint32_t& r1, uint32_t addr) {
    asm volatile("ldmatrix.sync.aligned.m8n8.x2.shared.b16 {%0,%1}, [%2];"
                 : "=r"(r0), "=r"(r1) : "r"(addr));
}

// ---------------- small kernels ----------------
__global__ void zero_counts_kernel() { if (threadIdx.x < E_) g_counts[threadIdx.x] = 0; }

__global__ void __launch_bounds__(256)
rmsnorm_kernel(const float* __restrict__ X, const float* __restrict__ W, float* __restrict__ Yo) {
    int t = blockIdx.x, tid = threadIdx.x;
    float4 x = ((const float4*)(X + (size_t)t * D_))[tid];
    float ss = x.x*x.x + x.y*x.y + x.z*x.z + x.w*x.w;
    __shared__ float red[256];
    red[tid] = ss; __syncthreads();
    for (int s = 128; s > 0; s >>= 1) { if (tid < s) red[tid] += red[tid + s]; __syncthreads(); }
    float inv = rsqrtf(red[0] * (1.0f / 1024.0f) + 1e-6f);
    float4 w = ((const float4*)W)[tid];
    float4 y;
    y.x = x.x*inv*w.x; y.y = x.y*inv*w.y; y.z = x.z*inv*w.z; y.w = x.w*inv*w.w;
    ((float4*)(Yo + (size_t)t * D_))[tid] = y;
}

__global__ void __launch_bounds__(256)
round_copy_kernel(const float* __restrict__ src, float* __restrict__ dst) {
    size_t i = (size_t)blockIdx.x * 256 + threadIdx.x;
    float4 v = ((const float4*)src)[i];
    v.x = tf32r(v.x); v.y = tf32r(v.y); v.z = tf32r(v.z); v.w = tf32r(v.w);
    ((float4*)dst)[i] = v;
}

__global__ void __launch_bounds__(256)
gather_round_kernel(const float* __restrict__ Hn) {
    int i = blockIdx.x * 256 + threadIdx.x;   // over NSLOT * D/4
    int slot = i >> 8, d4 = i & 255;
    int t = g_slot_token[slot];
    float4 v = ((const float4*)(Hn + (size_t)t * D_))[d4];
    v.x = tf32r(v.x); v.y = tf32r(v.y); v.z = tf32r(v.z); v.w = tf32r(v.w);
    ((float4*)(g_Ag + (size_t)slot * D_))[d4] = v;
}

// ---------------- dense fp32 FFMA2 GEMM (router-critical path; unchanged) ----------------
template<bool ADDRES>
__global__ void __launch_bounds__(256, 2)
gemm_nt(const float* __restrict__ A, const float* __restrict__ Bw,
        float* __restrict__ C, const float* __restrict__ Res, int K) {
    int m0b = blockIdx.y * 128, n0b = blockIdx.x * 128;
    __shared__ float As[16][132];
    __shared__ float Bs[16][132];
    int tid = threadIdx.x;
    int tx = tid & 15, ty = tid >> 4;
    int m0 = ty * 8, n0 = tx * 8;
    unsigned long long acc[8][4];
    #pragma unroll
    for (int i = 0; i < 8; i++)
        #pragma unroll
        for (int j = 0; j < 4; j++) acc[i][j] = 0ull;
    int lm[2], cc4[2];
    const float* aptr[2];
    const float* bptrs[2];
    #pragma unroll
    for (int r = 0; r < 2; r++) {
        int idx = tid + r * 256;
        int mm = idx >> 2, cc = idx & 3;
        cc4[r] = cc * 4; lm[r] = mm;
        aptr[r]  = A  + (size_t)(m0b + mm) * K + cc * 4;
        bptrs[r] = Bw + (size_t)(n0b + mm) * K + cc * 4;
    }
    for (int kt = 0; kt < K; kt += 16) {
        #pragma unroll
        for (int r = 0; r < 2; r++) {
            float4 v = *(const float4*)(aptr[r] + kt);
            As[cc4[r]+0][lm[r]] = v.x; As[cc4[r]+1][lm[r]] = v.y;
            As[cc4[r]+2][lm[r]] = v.z; As[cc4[r]+3][lm[r]] = v.w;
            float4 w = *(const float4*)(bptrs[r] + kt);
            Bs[cc4[r]+0][lm[r]] = w.x; Bs[cc4[r]+1][lm[r]] = w.y;
            Bs[cc4[r]+2][lm[r]] = w.z; Bs[cc4[r]+3][lm[r]] = w.w;
        }
        __syncthreads();
        #pragma unroll
        for (int k = 0; k < 16; k++) {
            float4 a0 = *(const float4*)&As[k][m0];
            float4 a1 = *(const float4*)&As[k][m0 + 4];
            unsigned long long b0 = *(const unsigned long long*)&Bs[k][n0];
            unsigned long long b1 = *(const unsigned long long*)&Bs[k][n0 + 2];
            unsigned long long b2 = *(const unsigned long long*)&Bs[k][n0 + 4];
            unsigned long long b3 = *(const unsigned long long*)&Bs[k][n0 + 6];
            float av[8] = {a0.x, a0.y, a0.z, a0.w, a1.x, a1.y, a1.z, a1.w};
            #pragma unroll
            for (int i = 0; i < 8; i++) {
                unsigned long long ad = dup2(av[i]);
                ffma2(acc[i][0], ad, b0); ffma2(acc[i][1], ad, b1);
                ffma2(acc[i][2], ad, b2); ffma2(acc[i][3], ad, b3);
            }
        }
        __syncthreads();
    }
    #pragma unroll
    for (int i = 0; i < 8; i++) {
        size_t crow = (size_t)(m0b + m0 + i) * D_;
        float2* cp = (float2*)(C + crow + n0b + n0);
        #pragma unroll
        for (int j = 0; j < 4; j++) {
            float2 v; memcpy(&v, &acc[i][j], 8);
            if (ADDRES) {
                float2 rr = *(const float2*)(Res + crow + n0b + n0 + j * 2);
                v.x += rr.x; v.y += rr.y;
            }
            cp[j] = v;
        }
    }
}

// ---------------- RoPE ----------------
__global__ void rope_kernel(float* __restrict__ qh, float* __restrict__ kh,
                            const float* __restrict__ cosb, const float* __restrict__ sinb) {
    int idx = blockIdx.x * blockDim.x + threadIdx.x;
    if (idx >= T_ * H_ * 32) return;
    int p = idx & 31, h = (idx >> 5) & (H_ - 1), t = idx >> 9, s = t & (S_ - 1);
    float c = cosb[s * 32 + p], sn = sinb[s * 32 + p];
    size_t off = (size_t)t * D_ + h * HD_ + 2 * p;
    float2 qv = *(float2*)(qh + off);
    float2 kv = *(float2*)(kh + off);
    float2 qo, ko;
    qo.x = (qv.x * c - qv.y * sn) * 0.125f;
    qo.y = (qv.x * sn + qv.y * c) * 0.125f;
    ko.x = kv.x * c - kv.y * sn;
    ko.y = kv.x * sn + kv.y * c;
    *(float2*)(qh + off) = qo;
    *(float2*)(kh + off) = ko;
}

// ---------------- attention (unchanged) ----------------
__global__ void __launch_bounds__(128)
attn_kernel(const float* __restrict__ Q, const float* __restrict__ Kh,
            const float* __restrict__ Vh, float* __restrict__ O) {
    int b = blockIdx.z, h = blockIdx.y, qt = blockIdx.x;
    int tid = threadIdx.x;
    int r = qt * 128 + tid;
    __shared__ float4 Ks[64][16];
    __shared__ float4 Vs[64][16];
    size_t qbase = ((size_t)(b * S_ + r)) * D_ + h * HD_;
    float4 q4[16];
    #pragma unroll
    for (int i = 0; i < 16; i++) q4[i] = *(const float4*)(Q + qbase + i * 4);
    float4 o4[16];
    #pragma unroll
    for (int i = 0; i < 16; i++) o4[i] = make_float4(0.f, 0.f, 0.f, 0.f);
    float mrow = -1e30f, l = 0.f;
    int ntiles = qt * 2 + 2;
    for (int kt = 0; kt < ntiles; kt++) {
        int k0 = kt * 64;
        int j = tid >> 1, half = (tid & 1) * 8;
        size_t kb = ((size_t)(b * S_ + k0 + j)) * D_ + h * HD_ + half * 4;
        #pragma unroll
        for (int i = 0; i < 8; i++) {
            Ks[j][half + i] = *(const float4*)(Kh + kb + i * 4);
            Vs[j][half + i] = *(const float4*)(Vh + kb + i * 4);
        }
        __syncthreads();
        int jmax = r - k0 + 1;
        if (jmax > 64) jmax = 64;
        for (int jj = 0; jj < jmax; jj++) {
            float s0 = 0.f, s1 = 0.f, s2 = 0.f, s3 = 0.f;
            #pragma unroll
            for (int i = 0; i < 16; i += 4) {
                float4 k0v = Ks[jj][i],   k1v = Ks[jj][i+1];
                float4 k2v = Ks[jj][i+2], k3v = Ks[jj][i+3];
                s0 = fmaf(q4[i].x,   k0v.x, fmaf(q4[i].y,   k0v.y, fmaf(q4[i].z,   k0v.z, fmaf(q4[i].w,   k0v.w, s0))));
                s1 = fmaf(q4[i+1].x, k1v.x, fmaf(q4[i+1].y, k1v.y, fmaf(q4[i+1].z, k1v.z, fmaf(q4[i+1].w, k1v.w, s1))));
                s2 = fmaf(q4[i+2].x, k2v.x, fmaf(q4[i+2].y, k2v.y, fmaf(q4[i+2].z, k2v.z, fmaf(q4[i+2].w, k2v.w, s2))));
                s3 = fmaf(q4[i+3].x, k3v.x, fmaf(q4[i+3].y, k3v.y, fmaf(q4[i+3].z, k3v.z, fmaf(q4[i+3].w, k3v.w, s3))));
            }
            float s = (s0 + s1) + (s2 + s3);
            if (s <= mrow) {
                float p = __expf(s - mrow);
                l += p;
                #pragma unroll
                for (int i = 0; i < 16; i++) {
                    float4 vv = Vs[jj][i];
                    o4[i].x = fmaf(p, vv.x, o4[i].x); o4[i].y = fmaf(p, vv.y, o4[i].y);
                    o4[i].z = fmaf(p, vv.z, o4[i].z); o4[i].w = fmaf(p, vv.w, o4[i].w);
                }
            } else {
                float esc = __expf(mrow - s);
                mrow = s;
                l = fmaf(l, esc, 1.f);
                #pragma unroll
                for (int i = 0; i < 16; i++) {
                    float4 vv = Vs[jj][i];
                    o4[i].x = fmaf(o4[i].x, esc, vv.x); o4[i].y = fmaf(o4[i].y, esc, vv.y);
                    o4[i].z = fmaf(o4[i].z, esc, vv.z); o4[i].w = fmaf(o4[i].w, esc, vv.w);
                }
            }
        }
        __syncthreads();
    }
    float inv = 1.f / l;
    #pragma unroll
    for (int i = 0; i < 16; i++) {
        float4 o = o4[i];
        o.x *= inv; o.y *= inv; o.z *= inv; o.w *= inv;
        *(float4*)(O + qbase + i * 4) = o;
    }
}

// ---------------- router / scan / assign (unchanged) ----------------
__global__ void __launch_bounds__(256)
router_kernel(const float* __restrict__ Hn, const float* __restrict__ RW,
              const float* __restrict__ RB) {
    int t = blockIdx.x;
    int w = threadIdx.x >> 5, lane = threadIdx.x & 31;
    const float* x = Hn + (size_t)t * D_;
    const float* rw = RW + (size_t)w * D_;
    float acc = 0.f;
    for (int d = lane * 4; d < D_; d += 128) {
        float4 xv = *(const float4*)(x + d);
        float4 wv = *(const float4*)(rw + d);
        acc += xv.x*wv.x + xv.y*wv.y + xv.z*wv.z + xv.w*wv.w;
    }
    #pragma unroll
    for (int o = 16; o; o >>= 1) acc += __shfl_xor_sync(0xffffffffu, acc, o);
    __shared__ float lg[E_];
    if (lane == 0) lg[w] = acc + RB[w];
    __syncthreads();
    if (threadIdx.x == 0) {
        float v0 = -1e30f, v1 = -1e30f; int i0 = 0, i1 = 0;
        #pragma unroll
        for (int e = 0; e < E_; e++) {
            float v = lg[e];
            if (v > v0) { v1 = v0; i1 = i0; v0 = v; i0 = e; }
            else if (v > v1) { v1 = v; i1 = e; }
        }
        float e1 = expf(v1 - v0);
        float inv = 1.f / (1.f + e1);
        g_topi[t*2] = i0; g_topi[t*2+1] = i1;
        g_gate[t*2] = inv; g_gate[t*2+1] = e1 * inv;
        atomicAdd(&g_counts[i0], 1);
        atomicAdd(&g_counts[i1], 1);
    }
}

__global__ void scan_kernel() {
    if (threadIdx.x == 0) {
        int o = 0;
        for (int e = 0; e < E_; e++) { g_offs[e] = o; g_cursor[e] = o; o += g_counts[e]; }
    }
}

__global__ void assign_kernel() {
    int t = blockIdx.x * blockDim.x + threadIdx.x;
    if (t >= T_) return;
    #pragma unroll
    for (int j = 0; j < 2; j++) {
        int e = g_topi[t*2+j];
        int slot = atomicAdd(&g_cursor[e], 1);
        g_slot_token[slot] = t;
        g_token_slot[t*2+j] = slot;
    }
}

// ================= MoE tf32 mma.sync GEMMs with ldmatrix =================
#define KC 64
#define STRD 68
#define OPBYTES (128*STRD*4)              // 34816 per operand per stage
#define W13_STAGE (3*OPBYTES)             // A + B1 + B3 = 104448
#define W13_SMEM  (2*W13_STAGE)           // 208896  (2-stage)
#define W2_STAGE  (2*OPBYTES)             // 69632
#define W2_SMEM   (3*W2_STAGE)            // 208896  (3-stage)

// fused: H1 = A@w1^T, H3 = A@w3^T, G = tf32(silu(H1)*H3). K = D_ = 1024.
__global__ void __launch_bounds__(256, 1)
moe_w13(const float* __restrict__ A, const float* __restrict__ W1,
        const float* __restrict__ W3, float* __restrict__ G) {
    int e = blockIdx.z;
    int cnt = g_counts[e];
    int m0b = blockIdx.y * 128;
    if (m0b >= cnt) return;
    int base = g_offs[e];
    int n0b = blockIdx.x * 128;
    const float* Arow  = A  + (size_t)(base + m0b) * D_;
    const float* B1row = W1 + (size_t)e * F_ * D_ + (size_t)n0b * D_;
    const float* B3row = W3 + (size_t)e * F_ * D_ + (size_t)n0b * D_;

    extern __shared__ float smf[];
    uint32_t sm0 = smem_u32(smf);

    int tid = threadIdx.x;
    int wid = tid >> 5, lane = tid & 31;
    int wm = wid >> 2, wn = wid & 3;           // warps 2(m) x 4(n)
    int g = lane >> 2, qd = lane & 3;

    // ldmatrix per-lane source offsets (bytes, relative to stage base)
    int rsel = lane >> 3;
    int rowA = (rsel & 1) * 8 + (lane & 7);
    int colA = (rsel >> 1) * 4;
    int rowB = lane & 7;
    int colB = ((lane >> 3) & 1) * 4;
    uint32_t offA[4], offB1[4], offB3[4];
    #pragma unroll
    for (int mi = 0; mi < 4; mi++)
        offA[mi] = ((wm * 64 + mi * 16 + rowA) * STRD + colA) * 4;
    #pragma unroll
    for (int ni = 0; ni < 4; ni++) {
        uint32_t o = ((wn * 32 + ni * 8 + rowB) * STRD + colB) * 4;
        offB1[ni] = OPBYTES + o;
        offB3[ni] = 2 * OPBYTES + o;
    }

    float c1[4][4][4], c3[4][4][4];
    #pragma unroll
    for (int mi = 0; mi < 4; mi++)
        #pragma unroll
        for (int ni = 0; ni < 4; ni++)
            #pragma unroll
            for (int r = 0; r < 4; r++) { c1[mi][ni][r] = 0.f; c3[mi][ni][r] = 0.f; }

    int lrow[8], lseg[8];
    #pragma unroll
    for (int j = 0; j < 8; j++) {
        int idx = tid + j * 256;
        lrow[j] = idx >> 4;
        lseg[j] = idx & 15;
    }

    const int NC = D_ / KC;   // 16

    // prologue: chunk 0 -> stage 0
    {
        uint32_t sb = sm0;
        #pragma unroll
        for (int j = 0; j < 8; j++) {
            uint32_t d = lrow[j] * (STRD * 4) + lseg[j] * 16;
            size_t go = (size_t)lrow[j] * D_ + lseg[j] * 4;
            cp16(sb + d, Arow + go);
            cp16(sb + OPBYTES + d, B1row + go);
            cp16(sb + 2 * OPBYTES + d, B3row + go);
        }
        CP_COMMIT();
    }

    for (int c = 0; c < NC; c++) {
        CP_WAIT0();
        __syncthreads();
        if (c + 1 < NC) {
            uint32_t sb = sm0 + ((c + 1) & 1) * W13_STAGE;
            #pragma unroll
            for (int j = 0; j < 8; j++) {
                uint32_t d = lrow[j] * (STRD * 4) + lseg[j] * 16;
                size_t go = (size_t)lrow[j] * D_ + (c + 1) * KC + lseg[j] * 4;
                cp16(sb + d, Arow + go);
                cp16(sb + OPBYTES + d, B1row + go);
                cp16(sb + 2 * OPBYTES + d, B3row + go);
            }
            CP_COMMIT();
        }
        uint32_t sb = sm0 + (c & 1) * W13_STAGE;
        #pragma unroll
        for (int ks = 0; ks < KC / 8; ks++) {
            uint32_t ko = sb + ks * 32;
            uint32_t a[4][4];
            #pragma unroll
            for (int mi = 0; mi < 4; mi++)
                ldsm4(a[mi][0], a[mi][1], a[mi][2], a[mi][3], offA[mi] + ko);
            uint32_t b[4][2];
            #pragma unroll
            for (int ni = 0; ni < 4; ni++) ldsm2(b[ni][0], b[ni][1], offB1[ni] + ko);
            #pragma unroll
            for (int mi = 0; mi < 4; mi++)
                #pragma unroll
                for (int ni = 0; ni < 4; ni++)
                    mma_tf32(c1[mi][ni][0], c1[mi][ni][1], c1[mi][ni][2], c1[mi][ni][3],
                             a[mi][0], a[mi][1], a[mi][2], a[mi][3], b[ni][0], b[ni][1]);
            #pragma unroll
            for (int ni = 0; ni < 4; ni++) ldsm2(b[ni][0], b[ni][1], offB3[ni] + ko);
            #pragma unroll
            for (int mi = 0; mi < 4; mi++)
                #pragma unroll
                for (int ni = 0; ni < 4; ni++)
                    mma_tf32(c3[mi][ni][0], c3[mi][ni][1], c3[mi][ni][2], c3[mi][ni][3],
                             a[mi][0], a[mi][1], a[mi][2], a[mi][3], b[ni][0], b[ni][1]);
        }
        __syncthreads();
    }

    // epilogue: G = tf32(silu(H1) * H3)
    #pragma unroll
    for (int mi = 0; mi < 4; mi++) {
        int mr0 = m0b + wm * 64 + mi * 16 + g;
        #pragma unroll
        for (int ni = 0; ni < 4; ni++) {
            int col = n0b + wn * 32 + ni * 8 + qd * 2;
            if (mr0 < cnt) {
                float h1 = c1[mi][ni][0], h3 = c3[mi][ni][0];
                float2 v;
                v.x = tf32r(h1 / (1.f + __expf(-h1)) * h3);
                h1 = c1[mi][ni][1]; h3 = c3[mi][ni][1];
                v.y = tf32r(h1 / (1.f + __expf(-h1)) * h3);
                *(float2*)(G + (size_t)(base + mr0) * F_ + col) = v;
            }
            if (mr0 + 8 < cnt) {
                float h1 = c1[mi][ni][2], h3 = c3[mi][ni][2];
                float2 v;
                v.x = tf32r(h1 / (1.f + __expf(-h1)) * h3);
                h1 = c1[mi][ni][3]; h3 = c3[mi][ni][3];
                v.y = tf32r(h1 / (1.f + __expf(-h1)) * h3);
                *(float2*)(G + (size_t)(base + mr0 + 8) * F_ + col) = v;
            }
        }
    }
}

// Y = G @ w2^T per expert. K = F_ = 4096, N = D_ = 1024. 3-stage.
__global__ void __launch_bounds__(256, 1)
moe_w2(const float* __restrict__ A, const float* __restrict__ Bw, float* __restrict__ Y) {
    int e = blockIdx.z;
    int cnt = g_counts[e];
    int m0b = blockIdx.y * 128;
    if (m0b >= cnt) return;
    int base = g_offs[e];
    int n0b = blockIdx.x * 128;
    const float* Arow = A  + (size_t)(base + m0b) * F_;
    const float* Brow = Bw + (size_t)e * D_ * F_ + (size_t)n0b * F_;

    extern __shared__ float smf[];
    uint32_t sm0 = smem_u32(smf);

    int tid = threadIdx.x;
    int wid = tid >> 5, lane = tid & 31;
    int wm = wid >> 2, wn = wid & 3;
    int g = lane >> 2, qd = lane & 3;

    int rsel = lane >> 3;
    int rowA = (rsel & 1) * 8 + (lane & 7);
    int colA = (rsel >> 1) * 4;
    int rowB = lane & 7;
    int colB = ((lane >> 3) & 1) * 4;
    uint32_t offA[4], offB[4];
    #pragma unroll
    for (int mi = 0; mi < 4; mi++)
        offA[mi] = ((wm * 64 + mi * 16 + rowA) * STRD + colA) * 4;
    #pragma unroll
    for (int ni = 0; ni < 4; ni++)
        offB[ni] = OPBYTES + ((wn * 32 + ni * 8 + rowB) * STRD + colB) * 4;

    float c[4][4][4];
    #pragma unroll
    for (int mi = 0; mi < 4; mi++)
        #pragma unroll
        for (int ni = 0; ni < 4; ni++)
            #pragma unroll
            for (int r = 0; r < 4; r++) c[mi][ni][r] = 0.f;

    int lrow[8], lseg[8];
    #pragma unroll
    for (int j = 0; j < 8; j++) {
        int idx = tid + j * 256;
        lrow[j] = idx >> 4;
        lseg[j] = idx & 15;
    }

    const int NC = F_ / KC;   // 64

    #pragma unroll
    for (int pc = 0; pc < 2; pc++) {
        uint32_t sb = sm0 + pc * W2_STAGE;
        #pragma unroll
        for (int j = 0; j < 8; j++) {
            uint32_t d = lrow[j] * (STRD * 4) + lseg[j] * 16;
            size_t go = (size_t)lrow[j] * F_ + pc * KC + lseg[j] * 4;
            cp16(sb + d, Arow + go);
            cp16(sb + OPBYTES + d, Brow + go);
        }
        CP_COMMIT();
    }

    for (int cix = 0; cix < NC; cix++) {
        CP_WAIT1();
        __syncthreads();
        if (cix + 2 < NC) {
            uint32_t sb = sm0 + ((cix + 2) % 3) * W2_STAGE;
            #pragma unroll
            for (int j = 0; j < 8; j++) {
                uint32_t d = lrow[j] * (STRD * 4) + lseg[j] * 16;
                size_t go = (size_t)lrow[j] * F_ + (cix + 2) * KC + lseg[j] * 4;
                cp16(sb + d, Arow + go);
                cp16(sb + OPBYTES + d, Brow + go);
            }
        }
        CP_COMMIT();
        uint32_t sb = sm0 + (cix % 3) * W2_STAGE;
        #pragma unroll
        for (int ks = 0; ks < KC / 8; ks++) {
            uint32_t ko = sb + ks * 32;
            uint32_t a[4][4];
            #pragma unroll
            for (int mi = 0; mi < 4; mi++)
                ldsm4(a[mi][0], a[mi][1], a[mi][2], a[mi][3], offA[mi] + ko);
            uint32_t b[4][2];
            #pragma unroll
            for (int ni = 0; ni < 4; ni++) ldsm2(b[ni][0], b[ni][1], offB[ni] + ko);
            #pragma unroll
            for (int mi = 0; mi < 4; mi++)
                #pragma unroll
                for (int ni = 0; ni < 4; ni++)
                    mma_tf32(c[mi][ni][0], c[mi][ni][1], c[mi][ni][2], c[mi][ni][3],
                             a[mi][0], a[mi][1], a[mi][2], a[mi][3], b[ni][0], b[ni][1]);
        }
        __syncthreads();
    }

    #pragma unroll
    for (int mi = 0; mi < 4; mi++) {
        int mr0 = m0b + wm * 64 + mi * 16 + g;
        #pragma unroll
        for (int ni = 0; ni < 4; ni++) {
            int col = n0b + wn * 32 + ni * 8 + qd * 2;
            if (mr0 < cnt) {
                float2 v; v.x = c[mi][ni][0]; v.y = c[mi][ni][1];
                *(float2*)(Y + (size_t)(base + mr0) * D_ + col) = v;
            }
            if (mr0 + 8 < cnt) {
                float2 v; v.x = c[mi][ni][2]; v.y = c[mi][ni][3];
                *(float2*)(Y + (size_t)(base + mr0 + 8) * D_ + col) = v;
            }
        }
    }
}

// ---------------- combine ----------------
__global__ void combine_kernel(const float* __restrict__ Hres, float* __restrict__ Out) {
    int i = blockIdx.x * 256 + threadIdx.x;
    int t = i >> 8, d4 = i & 255;
    float g0 = g_gate[t*2], g1 = g_gate[t*2+1];
    int s0 = g_token_slot[t*2], s1 = g_token_slot[t*2+1];
    float4 hv = ((const float4*)(Hres + (size_t)t * D_))[d4];
    float4 y0 = ((const float4*)(g_Y + (size_t)s0 * D_))[d4];
    float4 y1 = ((const float4*)(g_Y + (size_t)s1 * D_))[d4];
    float4 o;
    o.x = hv.x + g0*y0.x + g1*y1.x;
    o.y = hv.y + g0*y0.y + g1*y1.y;
    o.z = hv.z + g0*y0.z + g1*y1.z;
    o.w = hv.w + g0*y0.w + g1*y1.w;
    ((float4*)Out)[i] = o;
}

// ---------------- host ----------------
extern "C" void kernel_launch(void* const* d_in, const int* in_sizes, int n_in,
                              void* d_out, int out_size) {
    const float* q    = (const float*)d_in[0];
    const float* fcos = (const float*)d_in[3];
    const float* fsin = (const float*)d_in[4];
    const float* attw = (const float*)d_in[5];
    const float* ffnw = (const float*)d_in[6];
    const float* wq   = (const float*)d_in[7];
    const float* wk   = (const float*)d_in[8];
    const float* wv   = (const float*)d_in[9];
    const float* wo   = (const float*)d_in[10];
    const float* rw   = (const float*)d_in[11];
    const float* rb   = (const float*)d_in[12];
    const float* w1   = (const float*)d_in[13];
    const float* w2   = (const float*)d_in[14];
    const float* w3   = (const float*)d_in[15];
    float* out = (float*)d_out;

    float *xn, *qh, *kh, *vh, *attn, *hbuf, *hn, *Ag, *G, *Y, *w1r, *w2r, *w3r;
    cudaGetSymbolAddress((void**)&xn,   g_xn);
    cudaGetSymbolAddress((void**)&qh,   g_qh);
    cudaGetSymbolAddress((void**)&kh,   g_kh);
    cudaGetSymbolAddress((void**)&vh,   g_vh);
    cudaGetSymbolAddress((void**)&attn, g_attn);
    cudaGetSymbolAddress((void**)&hbuf, g_h);
    cudaGetSymbolAddress((void**)&hn,   g_hn);
    cudaGetSymbolAddress((void**)&Ag,   g_Ag);
    cudaGetSymbolAddress((void**)&G,    g_G);
    cudaGetSymbolAddress((void**)&Y,    g_Y);
    cudaGetSymbolAddress((void**)&w1r,  g_w1r);
    cudaGetSymbolAddress((void**)&w2r,  g_w2r);
    cudaGetSymbolAddress((void**)&w3r,  g_w3r);

    cudaFuncSetAttribute(moe_w13, cudaFuncAttributeMaxDynamicSharedMemorySize, W13_SMEM);
    cudaFuncSetAttribute(moe_w2,  cudaFuncAttributeMaxDynamicSharedMemorySize, W2_SMEM);

    const int WN4 = (int)((size_t)E_ * F_ * D_ / 4);
    round_copy_kernel<<<WN4 / 256, 256>>>(w1, w1r);
    round_copy_kernel<<<WN4 / 256, 256>>>(w2, w2r);
    round_copy_kernel<<<WN4 / 256, 256>>>(w3, w3r);

    zero_counts_kernel<<<1, 32>>>();
    rmsnorm_kernel<<<T_, 256>>>(q, attw, xn);

    dim3 gq(D_ / 128, T_ / 128);
    gemm_nt<false><<<gq, 256>>>(xn, wq, qh, nullptr, D_);
    gemm_nt<false><<<gq, 256>>>(xn, wk, kh, nullptr, D_);
    gemm_nt<false><<<gq, 256>>>(xn, wv, vh, nullptr, D_);

    rope_kernel<<<(T_ * H_ * 32 + 255) / 256, 256>>>(qh, kh, fcos, fsin);
    attn_kernel<<<dim3(S_ / 128, H_, B_), 128>>>(qh, kh, vh, attn);
    gemm_nt<true><<<gq, 256>>>(attn, wo, hbuf, q, D_);

    rmsnorm_kernel<<<T_, 256>>>(hbuf, ffnw, hn);
    router_kernel<<<T_, 256>>>(hn, rw, rb);
    scan_kernel<<<1, 1>>>();
    assign_kernel<<<T_ / 256, 256>>>();
    gather_round_kernel<<<NSLOT * (D_ / 4) / 256, 256>>>(hn);

    moe_w13<<<dim3(F_ / 128, NSLOT / 128, E_), 256, W13_SMEM>>>(Ag, w1r, w3r, G);
    moe_w2 <<<dim3(D_ / 128, NSLOT / 128, E_), 256, W2_SMEM>>>(G, w2r, Y);

    combine_kernel<<<T_ * D_ / 4 / 256, 256>>>(hbuf, out);
}

// round 8
// speedup vs baseline: 2.6297x; 1.2503x over previous
#include <cuda_runtime.h>
#include <cuda_fp16.h>
#include <math.h>
#include <stdint.h>

#define B_  4
#define S_  1024
#define D_  1024
#define H_  16
#define HD_ 64
#define T_  (B_*S_)
#define E_  8
#define F_  4096
#define NSLOT (T_*2)
#define NPAD  (NSLOT+128)

// ---------------- scratch ----------------
__device__ float g_xn  [T_*D_];
__device__ float g_qh  [T_*D_];
__device__ float g_kh  [T_*D_];
__device__ float g_vh  [T_*D_];
__device__ float g_attn[T_*D_];
__device__ float g_h   [T_*D_];
__device__ float g_hn  [T_*D_];
__device__ __half g_Ag [(size_t)NPAD*D_];    // gathered + fp16-rounded activations
__device__ __half g_G  [(size_t)NPAD*F_];    // G = fp16(silu(H1)*H3)
__device__ float g_Y   [(size_t)NSLOT*D_];
__device__ __half g_w1h[(size_t)E_*F_*D_];
__device__ __half g_w2h[(size_t)E_*D_*F_];
__device__ __half g_w3h[(size_t)E_*F_*D_];
__device__ int   g_topi[T_*2];
__device__ float g_gate[T_*2];
__device__ int   g_counts[E_];
__device__ int   g_offs[E_];
__device__ int   g_cursor[E_];
__device__ int   g_slot_token[NSLOT];
__device__ int   g_token_slot[T_*2];

// ---------------- helpers ----------------
__device__ __forceinline__ unsigned long long dup2(float a) {
    unsigned long long d;
    asm("mov.b64 %0, {%1, %1};" : "=l"(d) : "f"(a));
    return d;
}
__device__ __forceinline__ void ffma2(unsigned long long& c, unsigned long long a,
                                      unsigned long long b) {
    asm("fma.rn.f32x2 %0, %1, %2, %0;" : "+l"(c) : "l"(a), "l"(b));
}
__device__ __forceinline__ void cp16(uint32_t s, const void* g) {
    asm volatile("cp.async.cg.shared.global [%0], [%1], 16;" :: "r"(s), "l"(g));
}
__device__ __forceinline__ uint32_t smem_u32(const void* p) {
    uint32_t a;
    asm("{ .reg .u64 t; cvta.to.shared.u64 t, %1; cvt.u32.u64 %0, t; }" : "=r"(a) : "l"(p));
    return a;
}
#define CP_COMMIT() asm volatile("cp.async.commit_group;" ::: "memory")
#define CP_WAIT1()  asm volatile("cp.async.wait_group 1;" ::: "memory")
#define CP_WAIT2()  asm volatile("cp.async.wait_group 2;" ::: "memory")

__device__ __forceinline__ void mma_f16(float& c0, float& c1, float& c2, float& c3,
                                        uint32_t a0, uint32_t a1, uint32_t a2, uint32_t a3,
                                        uint32_t b0, uint32_t b1) {
    asm volatile("mma.sync.aligned.m16n8k16.row.col.f32.f16.f16.f32 "
                 "{%0,%1,%2,%3}, {%4,%5,%6,%7}, {%8,%9}, {%0,%1,%2,%3};"
                 : "+f"(c0), "+f"(c1), "+f"(c2), "+f"(c3)
                 : "r"(a0), "r"(a1), "r"(a2), "r"(a3), "r"(b0), "r"(b1));
}
__device__ __forceinline__ void ldsm4(uint32_t& r0, uint32_t& r1, uint32_t& r2, uint32_t& r3,
                                      uint32_t addr) {
    asm volatile("ldmatrix.sync.aligned.m8n8.x4.shared.b16 {%0,%1,%2,%3}, [%4];"
                 : "=r"(r0), "=r"(r1), "=r"(r2), "=r"(r3) : "r"(addr));
}
__device__ __forceinline__ void ldsm2(uint32_t& r0, uint32_t& r1, uint32_t addr) {
    asm volatile("ldmatrix.sync.aligned.m8n8.x2.shared.b16 {%0,%1}, [%2];"
                 : "=r"(r0), "=r"(r1) : "r"(addr));
}

// ---------------- small kernels ----------------
__global__ void zero_counts_kernel() { if (threadIdx.x < E_) g_counts[threadIdx.x] = 0; }

__global__ void __launch_bounds__(256)
rmsnorm_kernel(const float* __restrict__ X, const float* __restrict__ W, float* __restrict__ Yo) {
    int t = blockIdx.x, tid = threadIdx.x;
    float4 x = ((const float4*)(X + (size_t)t * D_))[tid];
    float ss = x.x*x.x + x.y*x.y + x.z*x.z + x.w*x.w;
    __shared__ float red[256];
    red[tid] = ss; __syncthreads();
    for (int s = 128; s > 0; s >>= 1) { if (tid < s) red[tid] += red[tid + s]; __syncthreads(); }
    float inv = rsqrtf(red[0] * (1.0f / 1024.0f) + 1e-6f);
    float4 w = ((const float4*)W)[tid];
    float4 y;
    y.x = x.x*inv*w.x; y.y = x.y*inv*w.y; y.z = x.z*inv*w.z; y.w = x.w*inv*w.w;
    ((float4*)(Yo + (size_t)t * D_))[tid] = y;
}

// fp32 -> fp16 (rna) weight copy
__global__ void __launch_bounds__(256)
round_copy_h(const float* __restrict__ src, __half* __restrict__ dst) {
    size_t i = (size_t)blockIdx.x * 256 + threadIdx.x;   // over n/4
    float4 v = ((const float4*)src)[i];
    __half2 h0 = __floats2half2_rn(v.x, v.y);
    __half2 h1 = __floats2half2_rn(v.z, v.w);
    uint2 o; o.x = *(uint32_t*)&h0; o.y = *(uint32_t*)&h1;
    ((uint2*)dst)[i] = o;
}

__global__ void __launch_bounds__(256)
gather_h_kernel(const float* __restrict__ Hn) {
    int i = blockIdx.x * 256 + threadIdx.x;   // over NSLOT * D/4
    int slot = i >> 8, d4 = i & 255;
    int t = g_slot_token[slot];
    float4 v = ((const float4*)(Hn + (size_t)t * D_))[d4];
    __half2 h0 = __floats2half2_rn(v.x, v.y);
    __half2 h1 = __floats2half2_rn(v.z, v.w);
    uint2 o; o.x = *(uint32_t*)&h0; o.y = *(uint32_t*)&h1;
    ((uint2*)(g_Ag + (size_t)slot * D_))[d4] = o;
}

// ---------------- dense fp32 FFMA2 GEMM (router-critical path; unchanged) ----------------
template<bool ADDRES>
__global__ void __launch_bounds__(256, 2)
gemm_nt(const float* __restrict__ A, const float* __restrict__ Bw,
        float* __restrict__ C, const float* __restrict__ Res, int K) {
    int m0b = blockIdx.y * 128, n0b = blockIdx.x * 128;
    __shared__ float As[16][132];
    __shared__ float Bs[16][132];
    int tid = threadIdx.x;
    int tx = tid & 15, ty = tid >> 4;
    int m0 = ty * 8, n0 = tx * 8;
    unsigned long long acc[8][4];
    #pragma unroll
    for (int i = 0; i < 8; i++)
        #pragma unroll
        for (int j = 0; j < 4; j++) acc[i][j] = 0ull;
    int lm[2], cc4[2];
    const float* aptr[2];
    const float* bptrs[2];
    #pragma unroll
    for (int r = 0; r < 2; r++) {
        int idx = tid + r * 256;
        int mm = idx >> 2, cc = idx & 3;
        cc4[r] = cc * 4; lm[r] = mm;
        aptr[r]  = A  + (size_t)(m0b + mm) * K + cc * 4;
        bptrs[r] = Bw + (size_t)(n0b + mm) * K + cc * 4;
    }
    for (int kt = 0; kt < K; kt += 16) {
        #pragma unroll
        for (int r = 0; r < 2; r++) {
            float4 v = *(const float4*)(aptr[r] + kt);
            As[cc4[r]+0][lm[r]] = v.x; As[cc4[r]+1][lm[r]] = v.y;
            As[cc4[r]+2][lm[r]] = v.z; As[cc4[r]+3][lm[r]] = v.w;
            float4 w = *(const float4*)(bptrs[r] + kt);
            Bs[cc4[r]+0][lm[r]] = w.x; Bs[cc4[r]+1][lm[r]] = w.y;
            Bs[cc4[r]+2][lm[r]] = w.z; Bs[cc4[r]+3][lm[r]] = w.w;
        }
        __syncthreads();
        #pragma unroll
        for (int k = 0; k < 16; k++) {
            float4 a0 = *(const float4*)&As[k][m0];
            float4 a1 = *(const float4*)&As[k][m0 + 4];
            unsigned long long b0 = *(const unsigned long long*)&Bs[k][n0];
            unsigned long long b1 = *(const unsigned long long*)&Bs[k][n0 + 2];
            unsigned long long b2 = *(const unsigned long long*)&Bs[k][n0 + 4];
            unsigned long long b3 = *(const unsigned long long*)&Bs[k][n0 + 6];
            float av[8] = {a0.x, a0.y, a0.z, a0.w, a1.x, a1.y, a1.z, a1.w};
            #pragma unroll
            for (int i = 0; i < 8; i++) {
                unsigned long long ad = dup2(av[i]);
                ffma2(acc[i][0], ad, b0); ffma2(acc[i][1], ad, b1);
                ffma2(acc[i][2], ad, b2); ffma2(acc[i][3], ad, b3);
            }
        }
        __syncthreads();
    }
    #pragma unroll
    for (int i = 0; i < 8; i++) {
        size_t crow = (size_t)(m0b + m0 + i) * D_;
        float2* cp = (float2*)(C + crow + n0b + n0);
        #pragma unroll
        for (int j = 0; j < 4; j++) {
            float2 v; memcpy(&v, &acc[i][j], 8);
            if (ADDRES) {
                float2 rr = *(const float2*)(Res + crow + n0b + n0 + j * 2);
                v.x += rr.x; v.y += rr.y;
            }
            cp[j] = v;
        }
    }
}

// ---------------- RoPE ----------------
__global__ void rope_kernel(float* __restrict__ qh, float* __restrict__ kh,
                            const float* __restrict__ cosb, const float* __restrict__ sinb) {
    int idx = blockIdx.x * blockDim.x + threadIdx.x;
    if (idx >= T_ * H_ * 32) return;
    int p = idx & 31, h = (idx >> 5) & (H_ - 1), t = idx >> 9, s = t & (S_ - 1);
    float c = cosb[s * 32 + p], sn = sinb[s * 32 + p];
    size_t off = (size_t)t * D_ + h * HD_ + 2 * p;
    float2 qv = *(float2*)(qh + off);
    float2 kv = *(float2*)(kh + off);
    float2 qo, ko;
    qo.x = (qv.x * c - qv.y * sn) * 0.125f;
    qo.y = (qv.x * sn + qv.y * c) * 0.125f;
    ko.x = kv.x * c - kv.y * sn;
    ko.y = kv.x * sn + kv.y * c;
    *(float2*)(qh + off) = qo;
    *(float2*)(kh + off) = ko;
}

// ---------------- attention (unchanged) ----------------
__global__ void __launch_bounds__(128)
attn_kernel(const float* __restrict__ Q, const float* __restrict__ Kh,
            const float* __restrict__ Vh, float* __restrict__ O) {
    int b = blockIdx.z, h = blockIdx.y, qt = blockIdx.x;
    int tid = threadIdx.x;
    int r = qt * 128 + tid;
    __shared__ float4 Ks[64][16];
    __shared__ float4 Vs[64][16];
    size_t qbase = ((size_t)(b * S_ + r)) * D_ + h * HD_;
    float4 q4[16];
    #pragma unroll
    for (int i = 0; i < 16; i++) q4[i] = *(const float4*)(Q + qbase + i * 4);
    float4 o4[16];
    #pragma unroll
    for (int i = 0; i < 16; i++) o4[i] = make_float4(0.f, 0.f, 0.f, 0.f);
    float mrow = -1e30f, l = 0.f;
    int ntiles = qt * 2 + 2;
    for (int kt = 0; kt < ntiles; kt++) {
        int k0 = kt * 64;
        int j = tid >> 1, half = (tid & 1) * 8;
        size_t kb = ((size_t)(b * S_ + k0 + j)) * D_ + h * HD_ + half * 4;
        #pragma unroll
        for (int i = 0; i < 8; i++) {
            Ks[j][half + i] = *(const float4*)(Kh + kb + i * 4);
            Vs[j][half + i] = *(const float4*)(Vh + kb + i * 4);
        }
        __syncthreads();
        int jmax = r - k0 + 1;
        if (jmax > 64) jmax = 64;
        for (int jj = 0; jj < jmax; jj++) {
            float s0 = 0.f, s1 = 0.f, s2 = 0.f, s3 = 0.f;
            #pragma unroll
            for (int i = 0; i < 16; i += 4) {
                float4 k0v = Ks[jj][i],   k1v = Ks[jj][i+1];
                float4 k2v = Ks[jj][i+2], k3v = Ks[jj][i+3];
                s0 = fmaf(q4[i].x,   k0v.x, fmaf(q4[i].y,   k0v.y, fmaf(q4[i].z,   k0v.z, fmaf(q4[i].w,   k0v.w, s0))));
                s1 = fmaf(q4[i+1].x, k1v.x, fmaf(q4[i+1].y, k1v.y, fmaf(q4[i+1].z, k1v.z, fmaf(q4[i+1].w, k1v.w, s1))));
                s2 = fmaf(q4[i+2].x, k2v.x, fmaf(q4[i+2].y, k2v.y, fmaf(q4[i+2].z, k2v.z, fmaf(q4[i+2].w, k2v.w, s2))));
                s3 = fmaf(q4[i+3].x, k3v.x, fmaf(q4[i+3].y, k3v.y, fmaf(q4[i+3].z, k3v.z, fmaf(q4[i+3].w, k3v.w, s3))));
            }
            float s = (s0 + s1) + (s2 + s3);
            if (s <= mrow) {
                float p = __expf(s - mrow);
                l += p;
                #pragma unroll
                for (int i = 0; i < 16; i++) {
                    float4 vv = Vs[jj][i];
                    o4[i].x = fmaf(p, vv.x, o4[i].x); o4[i].y = fmaf(p, vv.y, o4[i].y);
                    o4[i].z = fmaf(p, vv.z, o4[i].z); o4[i].w = fmaf(p, vv.w, o4[i].w);
                }
            } else {
                float esc = __expf(mrow - s);
                mrow = s;
                l = fmaf(l, esc, 1.f);
                #pragma unroll
                for (int i = 0; i < 16; i++) {
                    float4 vv = Vs[jj][i];
                    o4[i].x = fmaf(o4[i].x, esc, vv.x); o4[i].y = fmaf(o4[i].y, esc, vv.y);
                    o4[i].z = fmaf(o4[i].z, esc, vv.z); o4[i].w = fmaf(o4[i].w, esc, vv.w);
                }
            }
        }
        __syncthreads();
    }
    float inv = 1.f / l;
    #pragma unroll
    for (int i = 0; i < 16; i++) {
        float4 o = o4[i];
        o.x *= inv; o.y *= inv; o.z *= inv; o.w *= inv;
        *(float4*)(O + qbase + i * 4) = o;
    }
}

// ---------------- router / scan / assign (unchanged) ----------------
__global__ void __launch_bounds__(256)
router_kernel(const float* __restrict__ Hn, const float* __restrict__ RW,
              const float* __restrict__ RB) {
    int t = blockIdx.x;
    int w = threadIdx.x >> 5, lane = threadIdx.x & 31;
    const float* x = Hn + (size_t)t * D_;
    const float* rw = RW + (size_t)w * D_;
    float acc = 0.f;
    for (int d = lane * 4; d < D_; d += 128) {
        float4 xv = *(const float4*)(x + d);
        float4 wv = *(const float4*)(rw + d);
        acc += xv.x*wv.x + xv.y*wv.y + xv.z*wv.z + xv.w*wv.w;
    }
    #pragma unroll
    for (int o = 16; o; o >>= 1) acc += __shfl_xor_sync(0xffffffffu, acc, o);
    __shared__ float lg[E_];
    if (lane == 0) lg[w] = acc + RB[w];
    __syncthreads();
    if (threadIdx.x == 0) {
        float v0 = -1e30f, v1 = -1e30f; int i0 = 0, i1 = 0;
        #pragma unroll
        for (int e = 0; e < E_; e++) {
            float v = lg[e];
            if (v > v0) { v1 = v0; i1 = i0; v0 = v; i0 = e; }
            else if (v > v1) { v1 = v; i1 = e; }
        }
        float e1 = expf(v1 - v0);
        float inv = 1.f / (1.f + e1);
        g_topi[t*2] = i0; g_topi[t*2+1] = i1;
        g_gate[t*2] = inv; g_gate[t*2+1] = e1 * inv;
        atomicAdd(&g_counts[i0], 1);
        atomicAdd(&g_counts[i1], 1);
    }
}

__global__ void scan_kernel() {
    if (threadIdx.x == 0) {
        int o = 0;
        for (int e = 0; e < E_; e++) { g_offs[e] = o; g_cursor[e] = o; o += g_counts[e]; }
    }
}

__global__ void assign_kernel() {
    int t = blockIdx.x * blockDim.x + threadIdx.x;
    if (t >= T_) return;
    #pragma unroll
    for (int j = 0; j < 2; j++) {
        int e = g_topi[t*2+j];
        int slot = atomicAdd(&g_cursor[e], 1);
        g_slot_token[slot] = t;
        g_token_slot[t*2+j] = slot;
    }
}

// ================= MoE fp16 mma.sync (m16n8k16) GEMMs =================
#define KCH 64                         // k elements per chunk (fp16)
#define STRDH 72                       // halves per smem row (144B, conflict-free)
#define OPB (128*STRDH*2)              // 18432 B per operand per stage
#define W13_ST (3*OPB)                 // 55296
#define W13_SM (3*W13_ST)              // 165888 (3-stage)
#define W2_ST  (2*OPB)                 // 36864
#define W2_SM  (4*W2_ST)               // 147456 (4-stage)

// fused: H1 = A@w1^T, H3 = A@w3^T, G = fp16(silu(H1)*H3). K = D_ = 1024.
__global__ void __launch_bounds__(256, 1)
moe_w13(const __half* __restrict__ A, const __half* __restrict__ W1,
        const __half* __restrict__ W3, __half* __restrict__ G) {
    int e = blockIdx.z;
    int cnt = g_counts[e];
    int m0b = blockIdx.y * 128;
    if (m0b >= cnt) return;
    int base = g_offs[e];
    int n0b = blockIdx.x * 128;
    const __half* Arow  = A  + (size_t)(base + m0b) * D_;
    const __half* B1row = W1 + (size_t)e * F_ * D_ + (size_t)n0b * D_;
    const __half* B3row = W3 + (size_t)e * F_ * D_ + (size_t)n0b * D_;

    extern __shared__ __half smh[];
    uint32_t sm0 = smem_u32(smh);

    int tid = threadIdx.x;
    int wid = tid >> 5, lane = tid & 31;
    int wm = wid >> 2, wn = wid & 3;           // warps 2(m) x 4(n)
    int g = lane >> 2, qd = lane & 3;

    // ldmatrix lane offsets (bytes within operand)
    int arow = (lane & 7) + ((lane >> 3) & 1) * 8;
    int acolh = ((lane >> 4) & 1) * 8;
    int brow = lane & 7;
    int bcolh = ((lane >> 3) & 1) * 8;
    uint32_t offA[4], offB1[4], offB3[4];
    #pragma unroll
    for (int mi = 0; mi < 4; mi++)
        offA[mi] = ((wm * 64 + mi * 16 + arow) * STRDH + acolh) * 2;
    #pragma unroll
    for (int ni = 0; ni < 4; ni++) {
        uint32_t o = ((wn * 32 + ni * 8 + brow) * STRDH + bcolh) * 2;
        offB1[ni] = OPB + o;
        offB3[ni] = 2 * OPB + o;
    }

    float c1[4][4][4], c3[4][4][4];
    #pragma unroll
    for (int mi = 0; mi < 4; mi++)
        #pragma unroll
        for (int ni = 0; ni < 4; ni++)
            #pragma unroll
            for (int r = 0; r < 4; r++) { c1[mi][ni][r] = 0.f; c3[mi][ni][r] = 0.f; }

    int lrow[4], lseg[4];
    #pragma unroll
    for (int j = 0; j < 4; j++) {
        int idx = tid + j * 256;               // 0..1023
        lrow[j] = idx >> 3;
        lseg[j] = idx & 7;
    }

    const int NC = D_ / KCH;   // 16

    // prologue: chunks 0,1 -> stages 0,1
    #pragma unroll
    for (int pc = 0; pc < 2; pc++) {
        uint32_t sb = sm0 + pc * W13_ST;
        #pragma unroll
        for (int j = 0; j < 4; j++) {
            uint32_t d = lrow[j] * (STRDH * 2) + lseg[j] * 16;
            size_t go = (size_t)lrow[j] * D_ + pc * KCH + lseg[j] * 8;
            cp16(sb + d, Arow + go);
            cp16(sb + OPB + d, B1row + go);
            cp16(sb + 2 * OPB + d, B3row + go);
        }
        CP_COMMIT();
    }

    for (int c = 0; c < NC; c++) {
        CP_WAIT1();
        __syncthreads();
        if (c + 2 < NC) {
            uint32_t sb = sm0 + ((c + 2) % 3) * W13_ST;
            #pragma unroll
            for (int j = 0; j < 4; j++) {
                uint32_t d = lrow[j] * (STRDH * 2) + lseg[j] * 16;
                size_t go = (size_t)lrow[j] * D_ + (c + 2) * KCH + lseg[j] * 8;
                cp16(sb + d, Arow + go);
                cp16(sb + OPB + d, B1row + go);
                cp16(sb + 2 * OPB + d, B3row + go);
            }
        }
        CP_COMMIT();
        uint32_t sb = sm0 + (c % 3) * W13_ST;
        #pragma unroll
        for (int ks = 0; ks < KCH / 16; ks++) {
            uint32_t ko = sb + ks * 32;        // 16 halves = 32 B
            uint32_t a[4][4];
            #pragma unroll
            for (int mi = 0; mi < 4; mi++)
                ldsm4(a[mi][0], a[mi][1], a[mi][2], a[mi][3], offA[mi] + ko);
            uint32_t b[4][2];
            #pragma unroll
            for (int ni = 0; ni < 4; ni++) ldsm2(b[ni][0], b[ni][1], offB1[ni] + ko);
            #pragma unroll
            for (int mi = 0; mi < 4; mi++)
                #pragma unroll
                for (int ni = 0; ni < 4; ni++)
                    mma_f16(c1[mi][ni][0], c1[mi][ni][1], c1[mi][ni][2], c1[mi][ni][3],
                            a[mi][0], a[mi][1], a[mi][2], a[mi][3], b[ni][0], b[ni][1]);
            #pragma unroll
            for (int ni = 0; ni < 4; ni++) ldsm2(b[ni][0], b[ni][1], offB3[ni] + ko);
            #pragma unroll
            for (int mi = 0; mi < 4; mi++)
                #pragma unroll
                for (int ni = 0; ni < 4; ni++)
                    mma_f16(c3[mi][ni][0], c3[mi][ni][1], c3[mi][ni][2], c3[mi][ni][3],
                            a[mi][0], a[mi][1], a[mi][2], a[mi][3], b[ni][0], b[ni][1]);
        }
        __syncthreads();
    }

    // epilogue: G = fp16(silu(H1) * H3)
    #pragma unroll
    for (int mi = 0; mi < 4; mi++) {
        int mr0 = m0b + wm * 64 + mi * 16 + g;
        #pragma unroll
        for (int ni = 0; ni < 4; ni++) {
            int col = n0b + wn * 32 + ni * 8 + qd * 2;
            if (mr0 < cnt) {
                float h1 = c1[mi][ni][0], h3 = c3[mi][ni][0];
                float vx = h1 / (1.f + __expf(-h1)) * h3;
                h1 = c1[mi][ni][1]; h3 = c3[mi][ni][1];
                float vy = h1 / (1.f + __expf(-h1)) * h3;
                *(__half2*)(G + (size_t)(base + mr0) * F_ + col) = __floats2half2_rn(vx, vy);
            }
            if (mr0 + 8 < cnt) {
                float h1 = c1[mi][ni][2], h3 = c3[mi][ni][2];
                float vx = h1 / (1.f + __expf(-h1)) * h3;
                h1 = c1[mi][ni][3]; h3 = c3[mi][ni][3];
                float vy = h1 / (1.f + __expf(-h1)) * h3;
                *(__half2*)(G + (size_t)(base + mr0 + 8) * F_ + col) = __floats2half2_rn(vx, vy);
            }
        }
    }
}

// Y = G @ w2^T per expert. K = F_ = 4096, N = D_ = 1024. 4-stage.
__global__ void __launch_bounds__(256, 1)
moe_w2(const __half* __restrict__ A, const __half* __restrict__ Bw, float* __restrict__ Y) {
    int e = blockIdx.z;
    int cnt = g_counts[e];
    int m0b = blockIdx.y * 128;
    if (m0b >= cnt) return;
    int base = g_offs[e];
    int n0b = blockIdx.x * 128;
    const __half* Arow = A  + (size_t)(base + m0b) * F_;
    const __half* Brow = Bw + (size_t)e * D_ * F_ + (size_t)n0b * F_;

    extern __shared__ __half smh[];
    uint32_t sm0 = smem_u32(smh);

    int tid = threadIdx.x;
    int wid = tid >> 5, lane = tid & 31;
    int wm = wid >> 2, wn = wid & 3;
    int g = lane >> 2, qd = lane & 3;

    int arow = (lane & 7) + ((lane >> 3) & 1) * 8;
    int acolh = ((lane >> 4) & 1) * 8;
    int brow = lane & 7;
    int bcolh = ((lane >> 3) & 1) * 8;
    uint32_t offA[4], offB[4];
    #pragma unroll
    for (int mi = 0; mi < 4; mi++)
        offA[mi] = ((wm * 64 + mi * 16 + arow) * STRDH + acolh) * 2;
    #pragma unroll
    for (int ni = 0; ni < 4; ni++)
        offB[ni] = OPB + ((wn * 32 + ni * 8 + brow) * STRDH + bcolh) * 2;

    float c[4][4][4];
    #pragma unroll
    for (int mi = 0; mi < 4; mi++)
        #pragma unroll
        for (int ni = 0; ni < 4; ni++)
            #pragma unroll
            for (int r = 0; r < 4; r++) c[mi][ni][r] = 0.f;

    int lrow[4], lseg[4];
    #pragma unroll
    for (int j = 0; j < 4; j++) {
        int idx = tid + j * 256;
        lrow[j] = idx >> 3;
        lseg[j] = idx & 7;
    }

    const int NC = F_ / KCH;   // 64

    #pragma unroll
    for (int pc = 0; pc < 3; pc++) {
        uint32_t sb = sm0 + pc * W2_ST;
        #pragma unroll
        for (int j = 0; j < 4; j++) {
            uint32_t d = lrow[j] * (STRDH * 2) + lseg[j] * 16;
            size_t go = (size_t)lrow[j] * F_ + pc * KCH + lseg[j] * 8;
            cp16(sb + d, Arow + go);
            cp16(sb + OPB + d, Brow + go);
        }
        CP_COMMIT();
    }

    for (int cix = 0; cix < NC; cix++) {
        CP_WAIT2();
        __syncthreads();
        if (cix + 3 < NC) {
            uint32_t sb = sm0 + ((cix + 3) & 3) * W2_ST;
            #pragma unroll
            for (int j = 0; j < 4; j++) {
                uint32_t d = lrow[j] * (STRDH * 2) + lseg[j] * 16;
                size_t go = (size_t)lrow[j] * F_ + (cix + 3) * KCH + lseg[j] * 8;
                cp16(sb + d, Arow + go);
                cp16(sb + OPB + d, Brow + go);
            }
        }
        CP_COMMIT();
        uint32_t sb = sm0 + (cix & 3) * W2_ST;
        #pragma unroll
        for (int ks = 0; ks < KCH / 16; ks++) {
            uint32_t ko = sb + ks * 32;
            uint32_t a[4][4];
            #pragma unroll
            for (int mi = 0; mi < 4; mi++)
                ldsm4(a[mi][0], a[mi][1], a[mi][2], a[mi][3], offA[mi] + ko);
            uint32_t b[4][2];
            #pragma unroll
            for (int ni = 0; ni < 4; ni++) ldsm2(b[ni][0], b[ni][1], offB[ni] + ko);
            #pragma unroll
            for (int mi = 0; mi < 4; mi++)
                #pragma unroll
                for (int ni = 0; ni < 4; ni++)
                    mma_f16(c[mi][ni][0], c[mi][ni][1], c[mi][ni][2], c[mi][ni][3],
                            a[mi][0], a[mi][1], a[mi][2], a[mi][3], b[ni][0], b[ni][1]);
        }
        __syncthreads();
    }

    #pragma unroll
    for (int mi = 0; mi < 4; mi++) {
        int mr0 = m0b + wm * 64 + mi * 16 + g;
        #pragma unroll
        for (int ni = 0; ni < 4; ni++) {
            int col = n0b + wn * 32 + ni * 8 + qd * 2;
            if (mr0 < cnt) {
                float2 v; v.x = c[mi][ni][0]; v.y = c[mi][ni][1];
                *(float2*)(Y + (size_t)(base + mr0) * D_ + col) = v;
            }
            if (mr0 + 8 < cnt) {
                float2 v; v.x = c[mi][ni][2]; v.y = c[mi][ni][3];
                *(float2*)(Y + (size_t)(base + mr0 + 8) * D_ + col) = v;
            }
        }
    }
}

// ---------------- combine ----------------
__global__ void combine_kernel(const float* __restrict__ Hres, float* __restrict__ Out) {
    int i = blockIdx.x * 256 + threadIdx.x;
    int t = i >> 8, d4 = i & 255;
    float g0 = g_gate[t*2], g1 = g_gate[t*2+1];
    int s0 = g_token_slot[t*2], s1 = g_token_slot[t*2+1];
    float4 hv = ((const float4*)(Hres + (size_t)t * D_))[d4];
    float4 y0 = ((const float4*)(g_Y + (size_t)s0 * D_))[d4];
    float4 y1 = ((const float4*)(g_Y + (size_t)s1 * D_))[d4];
    float4 o;
    o.x = hv.x + g0*y0.x + g1*y1.x;
    o.y = hv.y + g0*y0.y + g1*y1.y;
    o.z = hv.z + g0*y0.z + g1*y1.z;
    o.w = hv.w + g0*y0.w + g1*y1.w;
    ((float4*)Out)[i] = o;
}

// ---------------- host ----------------
extern "C" void kernel_launch(void* const* d_in, const int* in_sizes, int n_in,
                              void* d_out, int out_size) {
    const float* q    = (const float*)d_in[0];
    const float* fcos = (const float*)d_in[3];
    const float* fsin = (const float*)d_in[4];
    const float* attw = (const float*)d_in[5];
    const float* ffnw = (const float*)d_in[6];
    const float* wq   = (const float*)d_in[7];
    const float* wk   = (const float*)d_in[8];
    const float* wv   = (const float*)d_in[9];
    const float* wo   = (const float*)d_in[10];
    const float* rw   = (const float*)d_in[11];
    const float* rb   = (const float*)d_in[12];
    const float* w1   = (const float*)d_in[13];
    const float* w2   = (const float*)d_in[14];
    const float* w3   = (const float*)d_in[15];
    float* out = (float*)d_out;

    float *xn, *qh, *kh, *vh, *attn, *hbuf, *hn, *Y;
    __half *Ag, *G, *w1h, *w2h, *w3h;
    cudaGetSymbolAddress((void**)&xn,   g_xn);
    cudaGetSymbolAddress((void**)&qh,   g_qh);
    cudaGetSymbolAddress((void**)&kh,   g_kh);
    cudaGetSymbolAddress((void**)&vh,   g_vh);
    cudaGetSymbolAddress((void**)&attn, g_attn);
    cudaGetSymbolAddress((void**)&hbuf, g_h);
    cudaGetSymbolAddress((void**)&hn,   g_hn);
    cudaGetSymbolAddress((void**)&Ag,   g_Ag);
    cudaGetSymbolAddress((void**)&G,    g_G);
    cudaGetSymbolAddress((void**)&Y,    g_Y);
    cudaGetSymbolAddress((void**)&w1h,  g_w1h);
    cudaGetSymbolAddress((void**)&w2h,  g_w2h);
    cudaGetSymbolAddress((void**)&w3h,  g_w3h);

    cudaFuncSetAttribute(moe_w13, cudaFuncAttributeMaxDynamicSharedMemorySize, W13_SM);
    cudaFuncSetAttribute(moe_w2,  cudaFuncAttributeMaxDynamicSharedMemorySize, W2_SM);

    const int WN4 = (int)((size_t)E_ * F_ * D_ / 4);
    round_copy_h<<<WN4 / 256, 256>>>(w1, w1h);
    round_copy_h<<<WN4 / 256, 256>>>(w2, w2h);
    round_copy_h<<<WN4 / 256, 256>>>(w3, w3h);

    zero_counts_kernel<<<1, 32>>>();
    rmsnorm_kernel<<<T_, 256>>>(q, attw, xn);

    dim3 gq(D_ / 128, T_ / 128);
    gemm_nt<false><<<gq, 256>>>(xn, wq, qh, nullptr, D_);
    gemm_nt<false><<<gq, 256>>>(xn, wk, kh, nullptr, D_);
    gemm_nt<false><<<gq, 256>>>(xn, wv, vh, nullptr, D_);

    rope_kernel<<<(T_ * H_ * 32 + 255) / 256, 256>>>(qh, kh, fcos, fsin);
    attn_kernel<<<dim3(S_ / 128, H_, B_), 128>>>(qh, kh, vh, attn);
    gemm_nt<true><<<gq, 256>>>(attn, wo, hbuf, q, D_);

    rmsnorm_kernel<<<T_, 256>>>(hbuf, ffnw, hn);
    router_kernel<<<T_, 256>>>(hn, rw, rb);
    scan_kernel<<<1, 1>>>();
    assign_kernel<<<T_ / 256, 256>>>();
    gather_h_kernel<<<NSLOT * (D_ / 4) / 256, 256>>>(hn);

    moe_w13<<<dim3(F_ / 128, NSLOT / 128, E_), 256, W13_SM>>>(Ag, w1h, w3h, G);
    moe_w2 <<<dim3(D_ / 128, NSLOT / 128, E_), 256, W2_SM>>>(G, w2h, Y);

    combine_kernel<<<T_ * D_ / 4 / 256, 256>>>(hbuf, out);
}

// round 12
// speedup vs baseline: 3.4782x; 1.3226x over previous
#include <cuda_runtime.h>
#include <cuda_fp16.h>
#include <math.h>
#include <stdint.h>

#define B_  4
#define S_  1024
#define D_  1024
#define H_  16
#define HD_ 64
#define T_  (B_*S_)
#define E_  8
#define F_  4096
#define NSLOT (T_*2)
#define NPAD  (NSLOT+128)
#define LOSCALE 2048.0f
#define INVLOSCALE (1.0f/2048.0f)

// ---------------- scratch ----------------
__device__ __half g_xnh[T_*D_];              // rmsnorm(q) hi/lo fp16 planes
__device__ __half g_xnl[T_*D_];
__device__ float  g_qkv[(size_t)3*T_*D_];    // q,k,v heads fp32 (planes)
__device__ __half g_aih[T_*D_];              // attention output hi/lo
__device__ __half g_ail[T_*D_];
__device__ float  g_h  [T_*D_];
__device__ float  g_hn [T_*D_];
__device__ __half g_wdh[(size_t)4*D_*D_];    // wq|wk|wv|wo hi
__device__ __half g_wdl[(size_t)4*D_*D_];    // lo (x2048)
__device__ __half g_Ag [(size_t)NPAD*D_];
__device__ __half g_G  [(size_t)NPAD*F_];
__device__ float  g_Y  [(size_t)NSLOT*D_];
__device__ __half g_w1h[(size_t)E_*F_*D_];
__device__ __half g_w2h[(size_t)E_*D_*F_];
__device__ __half g_w3h[(size_t)E_*F_*D_];
__device__ int   g_topi[T_*2];
__device__ float g_gate[T_*2];
__device__ int   g_counts[E_];
__device__ int   g_offs[E_];
__device__ int   g_cursor[E_];
__device__ int   g_slot_token[NSLOT];
__device__ int   g_token_slot[T_*2];

// ---------------- helpers ----------------
__device__ __forceinline__ void cp16(uint32_t s, const void* g) {
    asm volatile("cp.async.cg.shared.global [%0], [%1], 16;" :: "r"(s), "l"(g));
}
__device__ __forceinline__ uint32_t smem_u32(const void* p) {
    uint32_t a;
    asm("{ .reg .u64 t; cvta.to.shared.u64 t, %1; cvt.u32.u64 %0, t; }" : "=r"(a) : "l"(p));
    return a;
}
#define CP_COMMIT() asm volatile("cp.async.commit_group;" ::: "memory")
#define CP_WAIT1()  asm volatile("cp.async.wait_group 1;" ::: "memory")
#define CP_WAIT2()  asm volatile("cp.async.wait_group 2;" ::: "memory")

__device__ __forceinline__ void mma_f16(float& c0, float& c1, float& c2, float& c3,
                                        uint32_t a0, uint32_t a1, uint32_t a2, uint32_t a3,
                                        uint32_t b0, uint32_t b1) {
    asm volatile("mma.sync.aligned.m16n8k16.row.col.f32.f16.f16.f32 "
                 "{%0,%1,%2,%3}, {%4,%5,%6,%7}, {%8,%9}, {%0,%1,%2,%3};"
                 : "+f"(c0), "+f"(c1), "+f"(c2), "+f"(c3)
                 : "r"(a0), "r"(a1), "r"(a2), "r"(a3), "r"(b0), "r"(b1));
}
__device__ __forceinline__ void ldsm4(uint32_t& r0, uint32_t& r1, uint32_t& r2, uint32_t& r3,
                                      uint32_t addr) {
    asm volatile("ldmatrix.sync.aligned.m8n8.x4.shared.b16 {%0,%1,%2,%3}, [%4];"
                 : "=r"(r0), "=r"(r1), "=r"(r2), "=r"(r3) : "r"(addr));
}
__device__ __forceinline__ void ldsm2(uint32_t& r0, uint32_t& r1, uint32_t addr) {
    asm volatile("ldmatrix.sync.aligned.m8n8.x2.shared.b16 {%0,%1}, [%2];"
                 : "=r"(r0), "=r"(r1) : "r"(addr));
}
__device__ __forceinline__ void split_hl(float x, __half& hi, __half& lo) {
    hi = __float2half_rn(x);
    lo = __float2half_rn((x - __half2float(hi)) * LOSCALE);
}

// ---------------- small kernels ----------------
__global__ void zero_counts_kernel() { if (threadIdx.x < E_) g_counts[threadIdx.x] = 0; }

// rmsnorm -> hi/lo fp16 planes (feeds QKV 2xFP16 GEMM)
__global__ void __launch_bounds__(256)
rmsnorm_hl_kernel(const float* __restrict__ X, const float* __restrict__ W) {
    int t = blockIdx.x, tid = threadIdx.x;
    float4 x = ((const float4*)(X + (size_t)t * D_))[tid];
    float ss = x.x*x.x + x.y*x.y + x.z*x.z + x.w*x.w;
    __shared__ float red[256];
    red[tid] = ss; __syncthreads();
    for (int s = 128; s > 0; s >>= 1) { if (tid < s) red[tid] += red[tid + s]; __syncthreads(); }
    float inv = rsqrtf(red[0] * (1.0f / 1024.0f) + 1e-6f);
    float4 w = ((const float4*)W)[tid];
    float y0 = x.x*inv*w.x, y1 = x.y*inv*w.y, y2 = x.z*inv*w.z, y3 = x.w*inv*w.w;
    __half h0,h1,h2,h3, l0,l1,l2,l3;
    split_hl(y0,h0,l0); split_hl(y1,h1,l1); split_hl(y2,h2,l2); split_hl(y3,h3,l3);
    __half2 hh0 = __halves2half2(h0,h1), hh1 = __halves2half2(h2,h3);
    __half2 ll0 = __halves2half2(l0,l1), ll1 = __halves2half2(l2,l3);
    uint2 ho, lo;
    ho.x = *(uint32_t*)&hh0; ho.y = *(uint32_t*)&hh1;
    lo.x = *(uint32_t*)&ll0; lo.y = *(uint32_t*)&ll1;
    ((uint2*)(g_xnh + (size_t)t * D_))[tid] = ho;
    ((uint2*)(g_xnl + (size_t)t * D_))[tid] = lo;
}

// plain fp32 rmsnorm (feeds router + MoE gather)
__global__ void __launch_bounds__(256)
rmsnorm_kernel(const float* __restrict__ X, const float* __restrict__ W, float* __restrict__ Yo) {
    int t = blockIdx.x, tid = threadIdx.x;
    float4 x = ((const float4*)(X + (size_t)t * D_))[tid];
    float ss = x.x*x.x + x.y*x.y + x.z*x.z + x.w*x.w;
    __shared__ float red[256];
    red[tid] = ss; __syncthreads();
    for (int s = 128; s > 0; s >>= 1) { if (tid < s) red[tid] += red[tid + s]; __syncthreads(); }
    float inv = rsqrtf(red[0] * (1.0f / 1024.0f) + 1e-6f);
    float4 w = ((const float4*)W)[tid];
    float4 y;
    y.x = x.x*inv*w.x; y.y = x.y*inv*w.y; y.z = x.z*inv*w.z; y.w = x.w*inv*w.w;
    ((float4*)(Yo + (size_t)t * D_))[tid] = y;
}

// fp32 -> hi/lo fp16 weight decomposition
__global__ void __launch_bounds__(256)
decomp_w_kernel(const float* __restrict__ src, __half* __restrict__ dh,
                __half* __restrict__ dl) {
    size_t i = (size_t)blockIdx.x * 256 + threadIdx.x;  // over n/4
    float4 v = ((const float4*)src)[i];
    __half h0,h1,h2,h3, l0,l1,l2,l3;
    split_hl(v.x,h0,l0); split_hl(v.y,h1,l1); split_hl(v.z,h2,l2); split_hl(v.w,h3,l3);
    __half2 hh0 = __halves2half2(h0,h1), hh1 = __halves2half2(h2,h3);
    __half2 ll0 = __halves2half2(l0,l1), ll1 = __halves2half2(l2,l3);
    uint2 ho, lo;
    ho.x = *(uint32_t*)&hh0; ho.y = *(uint32_t*)&hh1;
    lo.x = *(uint32_t*)&ll0; lo.y = *(uint32_t*)&ll1;
    ((uint2*)dh)[i] = ho;
    ((uint2*)dl)[i] = lo;
}

// fp32 -> fp16 single (MoE weights)
__global__ void __launch_bounds__(256)
round_copy_h(const float* __restrict__ src, __half* __restrict__ dst) {
    size_t i = (size_t)blockIdx.x * 256 + threadIdx.x;
    float4 v = ((const float4*)src)[i];
    __half2 h0 = __floats2half2_rn(v.x, v.y);
    __half2 h1 = __floats2half2_rn(v.z, v.w);
    uint2 o; o.x = *(uint32_t*)&h0; o.y = *(uint32_t*)&h1;
    ((uint2*)dst)[i] = o;
}

__global__ void __launch_bounds__(256)
gather_h_kernel(const float* __restrict__ Hn) {
    int i = blockIdx.x * 256 + threadIdx.x;
    int slot = i >> 8, d4 = i & 255;
    int t = g_slot_token[slot];
    float4 v = ((const float4*)(Hn + (size_t)t * D_))[d4];
    __half2 h0 = __floats2half2_rn(v.x, v.y);
    __half2 h1 = __floats2half2_rn(v.z, v.w);
    uint2 o; o.x = *(uint32_t*)&h0; o.y = *(uint32_t*)&h1;
    ((uint2*)(g_Ag + (size_t)slot * D_))[d4] = o;
}

// ================= dense 2xFP16 compensated GEMM =================
// C[m, n] = sum_k A[m,k]*B[n,k], A = Ah + Al/2048, B = Bh + Bl/2048 (fp16 planes).
// C = Ah.Bh + (Ah.Bl + Al.Bh)/2048  (error ~2^-22 per elem => fp32-grade)
#define KCH 64
#define STRDH 72
#define OPB (128*STRDH*2)              // 18432 B per plane per stage
#define DX_ST (4*OPB)                  // Ah|Al|Bh|Bl = 73728
#define DX_SM (3*DX_ST)                // 221184 (3-stage)

template<bool ADDRES>
__global__ void __launch_bounds__(256, 1)
dense3x(const __half* __restrict__ Ah, const __half* __restrict__ Al,
        const __half* __restrict__ Bh, const __half* __restrict__ Bl,
        int bzoff, float* __restrict__ C, size_t czstride,
        const float* __restrict__ Res) {
    int z = blockIdx.z;
    int m0b = blockIdx.y * 128, n0b = blockIdx.x * 128;
    const __half* Ahrow = Ah + (size_t)m0b * D_;
    const __half* Alrow = Al + (size_t)m0b * D_;
    const __half* Bhrow = Bh + ((size_t)(bzoff + z) * 1024 + n0b) * D_;
    const __half* Blrow = Bl + ((size_t)(bzoff + z) * 1024 + n0b) * D_;
    float* Cz = C + (size_t)z * czstride;

    extern __shared__ __half smh[];
    uint32_t sm0 = smem_u32(smh);

    int tid = threadIdx.x;
    int wid = tid >> 5, lane = tid & 31;
    int wm = wid >> 2, wn = wid & 3;
    int g = lane >> 2, qd = lane & 3;

    int arow = (lane & 7) + ((lane >> 3) & 1) * 8;
    int acolh = ((lane >> 4) & 1) * 8;
    int brow = lane & 7;
    int bcolh = ((lane >> 3) & 1) * 8;
    uint32_t offAh[4], offBh[4];
    #pragma unroll
    for (int mi = 0; mi < 4; mi++)
        offAh[mi] = ((wm * 64 + mi * 16 + arow) * STRDH + acolh) * 2;
    #pragma unroll
    for (int ni = 0; ni < 4; ni++)
        offBh[ni] = 2 * OPB + ((wn * 32 + ni * 8 + brow) * STRDH + bcolh) * 2;

    float cm[4][4][4], cc[4][4][4];
    #pragma unroll
    for (int mi = 0; mi < 4; mi++)
        #pragma unroll
        for (int ni = 0; ni < 4; ni++)
            #pragma unroll
            for (int r = 0; r < 4; r++) { cm[mi][ni][r] = 0.f; cc[mi][ni][r] = 0.f; }

    int lrow[4], lseg[4];
    #pragma unroll
    for (int j = 0; j < 4; j++) {
        int idx = tid + j * 256;
        lrow[j] = idx >> 3;
        lseg[j] = idx & 7;
    }

    const int NC = D_ / KCH;   // 16

    #pragma unroll
    for (int pc = 0; pc < 2; pc++) {
        uint32_t sb = sm0 + pc * DX_ST;
        #pragma unroll
        for (int j = 0; j < 4; j++) {
            uint32_t d = lrow[j] * (STRDH * 2) + lseg[j] * 16;
            size_t go = (size_t)lrow[j] * D_ + pc * KCH + lseg[j] * 8;
            cp16(sb + d,           Ahrow + go);
            cp16(sb + OPB + d,     Alrow + go);
            cp16(sb + 2 * OPB + d, Bhrow + go);
            cp16(sb + 3 * OPB + d, Blrow + go);
        }
        CP_COMMIT();
    }

    for (int c = 0; c < NC; c++) {
        CP_WAIT1();
        __syncthreads();
        if (c + 2 < NC) {
            uint32_t sb = sm0 + ((c + 2) % 3) * DX_ST;
            #pragma unroll
            for (int j = 0; j < 4; j++) {
                uint32_t d = lrow[j] * (STRDH * 2) + lseg[j] * 16;
                size_t go = (size_t)lrow[j] * D_ + (c + 2) * KCH + lseg[j] * 8;
                cp16(sb + d,           Ahrow + go);
                cp16(sb + OPB + d,     Alrow + go);
                cp16(sb + 2 * OPB + d, Bhrow + go);
                cp16(sb + 3 * OPB + d, Blrow + go);
            }
        }
        CP_COMMIT();
        uint32_t sb = sm0 + (c % 3) * DX_ST;
        #pragma unroll
        for (int ks = 0; ks < KCH / 16; ks++) {
            uint32_t ko = sb + ks * 32;
            uint32_t ah[4][4], al[4][4];
            #pragma unroll
            for (int mi = 0; mi < 4; mi++) {
                ldsm4(ah[mi][0], ah[mi][1], ah[mi][2], ah[mi][3], offAh[mi] + ko);
                ldsm4(al[mi][0], al[mi][1], al[mi][2], al[mi][3], offAh[mi] + OPB + ko);
            }
            uint32_t bh[4][2], bl[4][2];
            #pragma unroll
            for (int ni = 0; ni < 4; ni++) {
                ldsm2(bh[ni][0], bh[ni][1], offBh[ni] + ko);
                ldsm2(bl[ni][0], bl[ni][1], offBh[ni] + OPB + ko);
            }
            #pragma unroll
            for (int mi = 0; mi < 4; mi++)
                #pragma unroll
                for (int ni = 0; ni < 4; ni++) {
                    mma_f16(cm[mi][ni][0], cm[mi][ni][1], cm[mi][ni][2], cm[mi][ni][3],
                            ah[mi][0], ah[mi][1], ah[mi][2], ah[mi][3], bh[ni][0], bh[ni][1]);
                    mma_f16(cc[mi][ni][0], cc[mi][ni][1], cc[mi][ni][2], cc[mi][ni][3],
                            ah[mi][0], ah[mi][1], ah[mi][2], ah[mi][3], bl[ni][0], bl[ni][1]);
                    mma_f16(cc[mi][ni][0], cc[mi][ni][1], cc[mi][ni][2], cc[mi][ni][3],
                            al[mi][0], al[mi][1], al[mi][2], al[mi][3], bh[ni][0], bh[ni][1]);
                }
        }
        __syncthreads();
    }

    #pragma unroll
    for (int mi = 0; mi < 4; mi++) {
        int mr0 = m0b + wm * 64 + mi * 16 + g;
        #pragma unroll
        for (int ni = 0; ni < 4; ni++) {
            int col = n0b + wn * 32 + ni * 8 + qd * 2;
            float2 v0, v1;
            v0.x = cm[mi][ni][0] + cc[mi][ni][0] * INVLOSCALE;
            v0.y = cm[mi][ni][1] + cc[mi][ni][1] * INVLOSCALE;
            v1.x = cm[mi][ni][2] + cc[mi][ni][2] * INVLOSCALE;
            v1.y = cm[mi][ni][3] + cc[mi][ni][3] * INVLOSCALE;
            if (ADDRES) {
                float2 r0 = *(const float2*)(Res + (size_t)mr0 * D_ + col);
                float2 r1 = *(const float2*)(Res + (size_t)(mr0 + 8) * D_ + col);
                v0.x += r0.x; v0.y += r0.y; v1.x += r1.x; v1.y += r1.y;
            }
            *(float2*)(Cz + (size_t)mr0 * D_ + col) = v0;
            *(float2*)(Cz + (size_t)(mr0 + 8) * D_ + col) = v1;
        }
    }
}

// ---------------- RoPE ----------------
__global__ void rope_kernel(float* __restrict__ qh, float* __restrict__ kh,
                            const float* __restrict__ cosb, const float* __restrict__ sinb) {
    int idx = blockIdx.x * blockDim.x + threadIdx.x;
    if (idx >= T_ * H_ * 32) return;
    int p = idx & 31, h = (idx >> 5) & (H_ - 1), t = idx >> 9, s = t & (S_ - 1);
    float c = cosb[s * 32 + p], sn = sinb[s * 32 + p];
    size_t off = (size_t)t * D_ + h * HD_ + 2 * p;
    float2 qv = *(float2*)(qh + off);
    float2 kv = *(float2*)(kh + off);
    float2 qo, ko;
    qo.x = (qv.x * c - qv.y * sn) * 0.125f;
    qo.y = (qv.x * sn + qv.y * c) * 0.125f;
    ko.x = kv.x * c - kv.y * sn;
    ko.y = kv.x * sn + kv.y * c;
    *(float2*)(qh + off) = qo;
    *(float2*)(kh + off) = ko;
}

// ---------------- attention (epilogue now emits hi/lo fp16) ----------------
__global__ void __launch_bounds__(128)
attn_kernel(const float* __restrict__ Q, const float* __restrict__ Kh,
            const float* __restrict__ Vh) {
    int b = blockIdx.z, h = blockIdx.y, qt = blockIdx.x;
    int tid = threadIdx.x;
    int r = qt * 128 + tid;
    __shared__ float4 Ks[64][16];
    __shared__ float4 Vs[64][16];
    size_t qbase = ((size_t)(b * S_ + r)) * D_ + h * HD_;
    float4 q4[16];
    #pragma unroll
    for (int i = 0; i < 16; i++) q4[i] = *(const float4*)(Q + qbase + i * 4);
    float4 o4[16];
    #pragma unroll
    for (int i = 0; i < 16; i++) o4[i] = make_float4(0.f, 0.f, 0.f, 0.f);
    float mrow = -1e30f, l = 0.f;
    int ntiles = qt * 2 + 2;
    for (int kt = 0; kt < ntiles; kt++) {
        int k0 = kt * 64;
        int j = tid >> 1, half = (tid & 1) * 8;
        size_t kb = ((size_t)(b * S_ + k0 + j)) * D_ + h * HD_ + half * 4;
        #pragma unroll
        for (int i = 0; i < 8; i++) {
            Ks[j][half + i] = *(const float4*)(Kh + kb + i * 4);
            Vs[j][half + i] = *(const float4*)(Vh + kb + i * 4);
        }
        __syncthreads();
        int jmax = r - k0 + 1;
        if (jmax > 64) jmax = 64;
        for (int jj = 0; jj < jmax; jj++) {
            float s0 = 0.f, s1 = 0.f, s2 = 0.f, s3 = 0.f;
            #pragma unroll
            for (int i = 0; i < 16; i += 4) {
                float4 k0v = Ks[jj][i],   k1v = Ks[jj][i+1];
                float4 k2v = Ks[jj][i+2], k3v = Ks[jj][i+3];
                s0 = fmaf(q4[i].x,   k0v.x, fmaf(q4[i].y,   k0v.y, fmaf(q4[i].z,   k0v.z, fmaf(q4[i].w,   k0v.w, s0))));
                s1 = fmaf(q4[i+1].x, k1v.x, fmaf(q4[i+1].y, k1v.y, fmaf(q4[i+1].z, k1v.z, fmaf(q4[i+1].w, k1v.w, s1))));
                s2 = fmaf(q4[i+2].x, k2v.x, fmaf(q4[i+2].y, k2v.y, fmaf(q4[i+2].z, k2v.z, fmaf(q4[i+2].w, k2v.w, s2))));
                s3 = fmaf(q4[i+3].x, k3v.x, fmaf(q4[i+3].y, k3v.y, fmaf(q4[i+3].z, k3v.z, fmaf(q4[i+3].w, k3v.w, s3))));
            }
            float s = (s0 + s1) + (s2 + s3);
            if (s <= mrow) {
                float p = __expf(s - mrow);
                l += p;
                #pragma unroll
                for (int i = 0; i < 16; i++) {
                    float4 vv = Vs[jj][i];
                    o4[i].x = fmaf(p, vv.x, o4[i].x); o4[i].y = fmaf(p, vv.y, o4[i].y);
                    o4[i].z = fmaf(p, vv.z, o4[i].z); o4[i].w = fmaf(p, vv.w, o4[i].w);
                }
            } else {
                float esc = __expf(mrow - s);
                mrow = s;
                l = fmaf(l, esc, 1.f);
                #pragma unroll
                for (int i = 0; i < 16; i++) {
                    float4 vv = Vs[jj][i];
                    o4[i].x = fmaf(o4[i].x, esc, vv.x); o4[i].y = fmaf(o4[i].y, esc, vv.y);
                    o4[i].z = fmaf(o4[i].z, esc, vv.z); o4[i].w = fmaf(o4[i].w, esc, vv.w);
                }
            }
        }
        __syncthreads();
    }
    float inv = 1.f / l;
    #pragma unroll
    for (int i = 0; i < 16; i++) {
        float v0 = o4[i].x * inv, v1 = o4[i].y * inv, v2 = o4[i].z * inv, v3 = o4[i].w * inv;
        __half h0,h1,h2,h3, l0,l1,l2,l3;
        split_hl(v0,h0,l0); split_hl(v1,h1,l1); split_hl(v2,h2,l2); split_hl(v3,h3,l3);
        __half2 hh0 = __halves2half2(h0,h1), hh1 = __halves2half2(h2,h3);
        __half2 ll0 = __halves2half2(l0,l1), ll1 = __halves2half2(l2,l3);
        uint2 ho, lo;
        ho.x = *(uint32_t*)&hh0; ho.y = *(uint32_t*)&hh1;
        lo.x = *(uint32_t*)&ll0; lo.y = *(uint32_t*)&ll1;
        *(uint2*)(g_aih + qbase + i * 4) = ho;
        *(uint2*)(g_ail + qbase + i * 4) = lo;
    }
}

// ---------------- router / scan / assign ----------------
__global__ void __launch_bounds__(256)
router_kernel(const float* __restrict__ Hn, const float* __restrict__ RW,
              const float* __restrict__ RB) {
    int t = blockIdx.x;
    int w = threadIdx.x >> 5, lane = threadIdx.x & 31;
    const float* x = Hn + (size_t)t * D_;
    const float* rw = RW + (size_t)w * D_;
    float acc = 0.f;
    for (int d = lane * 4; d < D_; d += 128) {
        float4 xv = *(const float4*)(x + d);
        float4 wv = *(const float4*)(rw + d);
        acc += xv.x*wv.x + xv.y*wv.y + xv.z*wv.z + xv.w*wv.w;
    }
    #pragma unroll
    for (int o = 16; o; o >>= 1) acc += __shfl_xor_sync(0xffffffffu, acc, o);
    __shared__ float lg[E_];
    if (lane == 0) lg[w] = acc + RB[w];
    __syncthreads();
    if (threadIdx.x == 0) {
        float v0 = -1e30f, v1 = -1e30f; int i0 = 0, i1 = 0;
        #pragma unroll
        for (int e = 0; e < E_; e++) {
            float v = lg[e];
            if (v > v0) { v1 = v0; i1 = i0; v0 = v; i0 = e; }
            else if (v > v1) { v1 = v; i1 = e; }
        }
        float e1 = expf(v1 - v0);
        float inv = 1.f / (1.f + e1);
        g_topi[t*2] = i0; g_topi[t*2+1] = i1;
        g_gate[t*2] = inv; g_gate[t*2+1] = e1 * inv;
        atomicAdd(&g_counts[i0], 1);
        atomicAdd(&g_counts[i1], 1);
    }
}

__global__ void scan_kernel() {
    if (threadIdx.x == 0) {
        int o = 0;
        for (int e = 0; e < E_; e++) { g_offs[e] = o; g_cursor[e] = o; o += g_counts[e]; }
    }
}

__global__ void assign_kernel() {
    int t = blockIdx.x * blockDim.x + threadIdx.x;
    if (t >= T_) return;
    #pragma unroll
    for (int j = 0; j < 2; j++) {
        int e = g_topi[t*2+j];
        int slot = atomicAdd(&g_cursor[e], 1);
        g_slot_token[slot] = t;
        g_token_slot[t*2+j] = slot;
    }
}

// ================= MoE fp16 mma.sync GEMMs (unchanged from R8) =================
#define W13_ST (3*OPB)                 // 55296
#define W13_SM (3*W13_ST)              // 165888 (3-stage)
#define W2_ST  (2*OPB)                 // 36864
#define W2_SM  (4*W2_ST)               // 147456 (4-stage)

__global__ void __launch_bounds__(256, 1)
moe_w13(const __half* __restrict__ A, const __half* __restrict__ W1,
        const __half* __restrict__ W3, __half* __restrict__ G) {
    int e = blockIdx.z;
    int cnt = g_counts[e];
    int m0b = blockIdx.y * 128;
    if (m0b >= cnt) return;
    int base = g_offs[e];
    int n0b = blockIdx.x * 128;
    const __half* Arow  = A  + (size_t)(base + m0b) * D_;
    const __half* B1row = W1 + (size_t)e * F_ * D_ + (size_t)n0b * D_;
    const __half* B3row = W3 + (size_t)e * F_ * D_ + (size_t)n0b * D_;

    extern __shared__ __half smh[];
    uint32_t sm0 = smem_u32(smh);

    int tid = threadIdx.x;
    int wid = tid >> 5, lane = tid & 31;
    int wm = wid >> 2, wn = wid & 3;
    int g = lane >> 2, qd = lane & 3;

    int arow = (lane & 7) + ((lane >> 3) & 1) * 8;
    int acolh = ((lane >> 4) & 1) * 8;
    int brow = lane & 7;
    int bcolh = ((lane >> 3) & 1) * 8;
    uint32_t offA[4], offB1[4], offB3[4];
    #pragma unroll
    for (int mi = 0; mi < 4; mi++)
        offA[mi] = ((wm * 64 + mi * 16 + arow) * STRDH + acolh) * 2;
    #pragma unroll
    for (int ni = 0; ni < 4; ni++) {
        uint32_t o = ((wn * 32 + ni * 8 + brow) * STRDH + bcolh) * 2;
        offB1[ni] = OPB + o;
        offB3[ni] = 2 * OPB + o;
    }

    float c1[4][4][4], c3[4][4][4];
    #pragma unroll
    for (int mi = 0; mi < 4; mi++)
        #pragma unroll
        for (int ni = 0; ni < 4; ni++)
            #pragma unroll
            for (int r = 0; r < 4; r++) { c1[mi][ni][r] = 0.f; c3[mi][ni][r] = 0.f; }

    int lrow[4], lseg[4];
    #pragma unroll
    for (int j = 0; j < 4; j++) {
        int idx = tid + j * 256;
        lrow[j] = idx >> 3;
        lseg[j] = idx & 7;
    }

    const int NC = D_ / KCH;   // 16

    #pragma unroll
    for (int pc = 0; pc < 2; pc++) {
        uint32_t sb = sm0 + pc * W13_ST;
        #pragma unroll
        for (int j = 0; j < 4; j++) {
            uint32_t d = lrow[j] * (STRDH * 2) + lseg[j] * 16;
            size_t go = (size_t)lrow[j] * D_ + pc * KCH + lseg[j] * 8;
            cp16(sb + d, Arow + go);
            cp16(sb + OPB + d, B1row + go);
            cp16(sb + 2 * OPB + d, B3row + go);
        }
        CP_COMMIT();
    }

    for (int c = 0; c < NC; c++) {
        CP_WAIT1();
        __syncthreads();
        if (c + 2 < NC) {
            uint32_t sb = sm0 + ((c + 2) % 3) * W13_ST;
            #pragma unroll
            for (int j = 0; j < 4; j++) {
                uint32_t d = lrow[j] * (STRDH * 2) + lseg[j] * 16;
                size_t go = (size_t)lrow[j] * D_ + (c + 2) * KCH + lseg[j] * 8;
                cp16(sb + d, Arow + go);
                cp16(sb + OPB + d, B1row + go);
                cp16(sb + 2 * OPB + d, B3row + go);
            }
        }
        CP_COMMIT();
        uint32_t sb = sm0 + (c % 3) * W13_ST;
        #pragma unroll
        for (int ks = 0; ks < KCH / 16; ks++) {
            uint32_t ko = sb + ks * 32;
            uint32_t a[4][4];
            #pragma unroll
            for (int mi = 0; mi < 4; mi++)
                ldsm4(a[mi][0], a[mi][1], a[mi][2], a[mi][3], offA[mi] + ko);
            uint32_t b[4][2];
            #pragma unroll
            for (int ni = 0; ni < 4; ni++) ldsm2(b[ni][0], b[ni][1], offB1[ni] + ko);
            #pragma unroll
            for (int mi = 0; mi < 4; mi++)
                #pragma unroll
                for (int ni = 0; ni < 4; ni++)
                    mma_f16(c1[mi][ni][0], c1[mi][ni][1], c1[mi][ni][2], c1[mi][ni][3],
                            a[mi][0], a[mi][1], a[mi][2], a[mi][3], b[ni][0], b[ni][1]);
            #pragma unroll
            for (int ni = 0; ni < 4; ni++) ldsm2(b[ni][0], b[ni][1], offB3[ni] + ko);
            #pragma unroll
            for (int mi = 0; mi < 4; mi++)
                #pragma unroll
                for (int ni = 0; ni < 4; ni++)
                    mma_f16(c3[mi][ni][0], c3[mi][ni][1], c3[mi][ni][2], c3[mi][ni][3],
                            a[mi][0], a[mi][1], a[mi][2], a[mi][3], b[ni][0], b[ni][1]);
        }
        __syncthreads();
    }

    #pragma unroll
    for (int mi = 0; mi < 4; mi++) {
        int mr0 = m0b + wm * 64 + mi * 16 + g;
        #pragma unroll
        for (int ni = 0; ni < 4; ni++) {
            int col = n0b + wn * 32 + ni * 8 + qd * 2;
            if (mr0 < cnt) {
                float h1 = c1[mi][ni][0], h3 = c3[mi][ni][0];
                float vx = h1 / (1.f + __expf(-h1)) * h3;
                h1 = c1[mi][ni][1]; h3 = c3[mi][ni][1];
                float vy = h1 / (1.f + __expf(-h1)) * h3;
                *(__half2*)(G + (size_t)(base + mr0) * F_ + col) = __floats2half2_rn(vx, vy);
            }
            if (mr0 + 8 < cnt) {
                float h1 = c1[mi][ni][2], h3 = c3[mi][ni][2];
                float vx = h1 / (1.f + __expf(-h1)) * h3;
                h1 = c1[mi][ni][3]; h3 = c3[mi][ni][3];
                float vy = h1 / (1.f + __expf(-h1)) * h3;
                *(__half2*)(G + (size_t)(base + mr0 + 8) * F_ + col) = __floats2half2_rn(vx, vy);
            }
        }
    }
}

__global__ void __launch_bounds__(256, 1)
moe_w2(const __half* __restrict__ A, const __half* __restrict__ Bw, float* __restrict__ Y) {
    int e = blockIdx.z;
    int cnt = g_counts[e];
    int m0b = blockIdx.y * 128;
    if (m0b >= cnt) return;
    int base = g_offs[e];
    int n0b = blockIdx.x * 128;
    const __half* Arow = A  + (size_t)(base + m0b) * F_;
    const __half* Brow = Bw + (size_t)e * D_ * F_ + (size_t)n0b * F_;

    extern __shared__ __half smh[];
    uint32_t sm0 = smem_u32(smh);

    int tid = threadIdx.x;
    int wid = tid >> 5, lane = tid & 31;
    int wm = wid >> 2, wn = wid & 3;
    int g = lane >> 2, qd = lane & 3;

    int arow = (lane & 7) + ((lane >> 3) & 1) * 8;
    int acolh = ((lane >> 4) & 1) * 8;
    int brow = lane & 7;
    int bcolh = ((lane >> 3) & 1) * 8;
    uint32_t offA[4], offB[4];
    #pragma unroll
    for (int mi = 0; mi < 4; mi++)
        offA[mi] = ((wm * 64 + mi * 16 + arow) * STRDH + acolh) * 2;
    #pragma unroll
    for (int ni = 0; ni < 4; ni++)
        offB[ni] = OPB + ((wn * 32 + ni * 8 + brow) * STRDH + bcolh) * 2;

    float c[4][4][4];
    #pragma unroll
    for (int mi = 0; mi < 4; mi++)
        #pragma unroll
        for (int ni = 0; ni < 4; ni++)
            #pragma unroll
            for (int r = 0; r < 4; r++) c[mi][ni][r] = 0.f;

    int lrow[4], lseg[4];
    #pragma unroll
    for (int j = 0; j < 4; j++) {
        int idx = tid + j * 256;
        lrow[j] = idx >> 3;
        lseg[j] = idx & 7;
    }

    const int NC = F_ / KCH;   // 64

    #pragma unroll
    for (int pc = 0; pc < 3; pc++) {
        uint32_t sb = sm0 + pc * W2_ST;
        #pragma unroll
        for (int j = 0; j < 4; j++) {
            uint32_t d = lrow[j] * (STRDH * 2) + lseg[j] * 16;
            size_t go = (size_t)lrow[j] * F_ + pc * KCH + lseg[j] * 8;
            cp16(sb + d, Arow + go);
            cp16(sb + OPB + d, Brow + go);
        }
        CP_COMMIT();
    }

    for (int cix = 0; cix < NC; cix++) {
        CP_WAIT2();
        __syncthreads();
        if (cix + 3 < NC) {
            uint32_t sb = sm0 + ((cix + 3) & 3) * W2_ST;
            #pragma unroll
            for (int j = 0; j < 4; j++) {
                uint32_t d = lrow[j] * (STRDH * 2) + lseg[j] * 16;
                size_t go = (size_t)lrow[j] * F_ + (cix + 3) * KCH + lseg[j] * 8;
                cp16(sb + d, Arow + go);
                cp16(sb + OPB + d, Brow + go);
            }
        }
        CP_COMMIT();
        uint32_t sb = sm0 + (cix & 3) * W2_ST;
        #pragma unroll
        for (int ks = 0; ks < KCH / 16; ks++) {
            uint32_t ko = sb + ks * 32;
            uint32_t a[4][4];
            #pragma unroll
            for (int mi = 0; mi < 4; mi++)
                ldsm4(a[mi][0], a[mi][1], a[mi][2], a[mi][3], offA[mi] + ko);
            uint32_t b[4][2];
            #pragma unroll
            for (int ni = 0; ni < 4; ni++) ldsm2(b[ni][0], b[ni][1], offB[ni] + ko);
            #pragma unroll
            for (int mi = 0; mi < 4; mi++)
                #pragma unroll
                for (int ni = 0; ni < 4; ni++)
                    mma_f16(c[mi][ni][0], c[mi][ni][1], c[mi][ni][2], c[mi][ni][3],
                            a[mi][0], a[mi][1], a[mi][2], a[mi][3], b[ni][0], b[ni][1]);
        }
        __syncthreads();
    }

    #pragma unroll
    for (int mi = 0; mi < 4; mi++) {
        int mr0 = m0b + wm * 64 + mi * 16 + g;
        #pragma unroll
        for (int ni = 0; ni < 4; ni++) {
            int col = n0b + wn * 32 + ni * 8 + qd * 2;
            if (mr0 < cnt) {
                float2 v; v.x = c[mi][ni][0]; v.y = c[mi][ni][1];
                *(float2*)(Y + (size_t)(base + mr0) * D_ + col) = v;
            }
            if (mr0 + 8 < cnt) {
                float2 v; v.x = c[mi][ni][2]; v.y = c[mi][ni][3];
                *(float2*)(Y + (size_t)(base + mr0 + 8) * D_ + col) = v;
            }
        }
    }
}

// ---------------- combine ----------------
__global__ void combine_kernel(const float* __restrict__ Hres, float* __restrict__ Out) {
    int i = blockIdx.x * 256 + threadIdx.x;
    int t = i >> 8, d4 = i & 255;
    float g0 = g_gate[t*2], g1 = g_gate[t*2+1];
    int s0 = g_token_slot[t*2], s1 = g_token_slot[t*2+1];
    float4 hv = ((const float4*)(Hres + (size_t)t * D_))[d4];
    float4 y0 = ((const float4*)(g_Y + (size_t)s0 * D_))[d4];
    float4 y1 = ((const float4*)(g_Y + (size_t)s1 * D_))[d4];
    float4 o;
    o.x = hv.x + g0*y0.x + g1*y1.x;
    o.y = hv.y + g0*y0.y + g1*y1.y;
    o.z = hv.z + g0*y0.z + g1*y1.z;
    o.w = hv.w + g0*y0.w + g1*y1.w;
    ((float4*)Out)[i] = o;
}

// ---------------- host ----------------
extern "C" void kernel_launch(void* const* d_in, const int* in_sizes, int n_in,
                              void* d_out, int out_size) {
    const float* q    = (const float*)d_in[0];
    const float* fcos = (const float*)d_in[3];
    const float* fsin = (const float*)d_in[4];
    const float* attw = (const float*)d_in[5];
    const float* ffnw = (const float*)d_in[6];
    const float* wq   = (const float*)d_in[7];
    const float* wk   = (const float*)d_in[8];
    const float* wv   = (const float*)d_in[9];
    const float* wo   = (const float*)d_in[10];
    const float* rw   = (const float*)d_in[11];
    const float* rb   = (const float*)d_in[12];
    const float* w1   = (const float*)d_in[13];
    const float* w2   = (const float*)d_in[14];
    const float* w3   = (const float*)d_in[15];
    float* out = (float*)d_out;

    float *qkv, *hbuf, *hn, *Y;
    __half *xnh, *xnl, *aih, *ail, *wdh, *wdl, *Ag, *G, *w1h, *w2h, *w3h;
    cudaGetSymbolAddress((void**)&xnh,  g_xnh);
    cudaGetSymbolAddress((void**)&xnl,  g_xnl);
    cudaGetSymbolAddress((void**)&qkv,  g_qkv);
    cudaGetSymbolAddress((void**)&aih,  g_aih);
    cudaGetSymbolAddress((void**)&ail,  g_ail);
    cudaGetSymbolAddress((void**)&hbuf, g_h);
    cudaGetSymbolAddress((void**)&hn,   g_hn);
    cudaGetSymbolAddress((void**)&wdh,  g_wdh);
    cudaGetSymbolAddress((void**)&wdl,  g_wdl);
    cudaGetSymbolAddress((void**)&Ag,   g_Ag);
    cudaGetSymbolAddress((void**)&G,    g_G);
    cudaGetSymbolAddress((void**)&Y,    g_Y);
    cudaGetSymbolAddress((void**)&w1h,  g_w1h);
    cudaGetSymbolAddress((void**)&w2h,  g_w2h);
    cudaGetSymbolAddress((void**)&w3h,  g_w3h);

    cudaFuncSetAttribute(dense3x<false>, cudaFuncAttributeMaxDynamicSharedMemorySize, DX_SM);
    cudaFuncSetAttribute(dense3x<true>,  cudaFuncAttributeMaxDynamicSharedMemorySize, DX_SM);
    cudaFuncSetAttribute(moe_w13, cudaFuncAttributeMaxDynamicSharedMemorySize, W13_SM);
    cudaFuncSetAttribute(moe_w2,  cudaFuncAttributeMaxDynamicSharedMemorySize, W2_SM);

    const int DD4 = D_ * D_ / 4;
    decomp_w_kernel<<<DD4 / 256, 256>>>(wq, wdh,               wdl);
    decomp_w_kernel<<<DD4 / 256, 256>>>(wk, wdh + D_*D_,       wdl + D_*D_);
    decomp_w_kernel<<<DD4 / 256, 256>>>(wv, wdh + 2*(size_t)D_*D_, wdl + 2*(size_t)D_*D_);
    decomp_w_kernel<<<DD4 / 256, 256>>>(wo, wdh + 3*(size_t)D_*D_, wdl + 3*(size_t)D_*D_);

    const int WN4 = (int)((size_t)E_ * F_ * D_ / 4);
    round_copy_h<<<WN4 / 256, 256>>>(w1, w1h);
    round_copy_h<<<WN4 / 256, 256>>>(w2, w2h);
    round_copy_h<<<WN4 / 256, 256>>>(w3, w3h);

    zero_counts_kernel<<<1, 32>>>();
    rmsnorm_hl_kernel<<<T_, 256>>>(q, attw);

    // QKV: one launch, z selects weight plane and output plane
    dense3x<false><<<dim3(8, 32, 3), 256, DX_SM>>>(xnh, xnl, wdh, wdl, 0,
                                                   qkv, (size_t)T_ * D_, nullptr);

    rope_kernel<<<(T_ * H_ * 32 + 255) / 256, 256>>>(qkv, qkv + (size_t)T_ * D_, fcos, fsin);
    attn_kernel<<<dim3(S_ / 128, H_, B_), 128>>>(qkv, qkv + (size_t)T_ * D_,
                                                 qkv + 2 * (size_t)T_ * D_);

    // WO + residual(q): weight plane 3
    dense3x<true><<<dim3(8, 32, 1), 256, DX_SM>>>(aih, ail, wdh, wdl, 3,
                                                  hbuf, 0, q);

    rmsnorm_kernel<<<T_, 256>>>(hbuf, ffnw, hn);
    router_kernel<<<T_, 256>>>(hn, rw, rb);
    scan_kernel<<<1, 1>>>();
    assign_kernel<<<T_ / 256, 256>>>();
    gather_h_kernel<<<NSLOT * (D_ / 4) / 256, 256>>>(hn);

    moe_w13<<<dim3(F_ / 128, NSLOT / 128, E_), 256, W13_SM>>>(Ag, w1h, w3h, G);
    moe_w2 <<<dim3(D_ / 128, NSLOT / 128, E_), 256, W2_SM>>>(G, w2h, Y);

    combine_kernel<<<T_ * D_ / 4 / 256, 256>>>(hbuf, out);
}

// round 14
// speedup vs baseline: 3.5869x; 1.0313x over previous
#include <cuda_runtime.h>
#include <cuda_fp16.h>
#include <math.h>
#include <stdint.h>

#define B_  4
#define S_  1024
#define D_  1024
#define H_  16
#define HD_ 64
#define T_  (B_*S_)
#define E_  8
#define F_  4096
#define NSLOT (T_*2)
#define NPAD  (NSLOT+128)
#define LOSCALE 2048.0f
#define INVLOSCALE (1.0f/2048.0f)

// ---------------- scratch ----------------
__device__ __half g_xnh[T_*D_];
__device__ __half g_xnl[T_*D_];
__device__ float  g_qkv[(size_t)3*T_*D_];
__device__ __half g_aih[T_*D_];
__device__ __half g_ail[T_*D_];
__device__ float  g_h  [T_*D_];
__device__ float  g_hn [T_*D_];
__device__ __half g_wdh[(size_t)4*D_*D_];
__device__ __half g_wdl[(size_t)4*D_*D_];
__device__ __half g_Ag [(size_t)NPAD*D_];
__device__ __half g_G  [(size_t)NPAD*F_];
__device__ float  g_Y  [(size_t)NSLOT*D_];
__device__ __half g_w1h[(size_t)E_*F_*D_];
__device__ __half g_w2h[(size_t)E_*D_*F_];
__device__ __half g_w3h[(size_t)E_*F_*D_];
__device__ int   g_topi[T_*2];
__device__ float g_gate[T_*2];
__device__ int   g_counts[E_];
__device__ int   g_offs[E_];
__device__ int   g_cursor[E_];
__device__ int   g_slot_token[NSLOT];
__device__ int   g_token_slot[T_*2];

// ---------------- helpers ----------------
__device__ __forceinline__ void cp16(uint32_t s, const void* g) {
    asm volatile("cp.async.cg.shared.global [%0], [%1], 16;" :: "r"(s), "l"(g));
}
__device__ __forceinline__ uint32_t smem_u32(const void* p) {
    uint32_t a;
    asm("{ .reg .u64 t; cvta.to.shared.u64 t, %1; cvt.u32.u64 %0, t; }" : "=r"(a) : "l"(p));
    return a;
}
#define CP_COMMIT() asm volatile("cp.async.commit_group;" ::: "memory")
#define CP_WAIT1()  asm volatile("cp.async.wait_group 1;" ::: "memory")

__device__ __forceinline__ void mma_f16(float& c0, float& c1, float& c2, float& c3,
                                        uint32_t a0, uint32_t a1, uint32_t a2, uint32_t a3,
                                        uint32_t b0, uint32_t b1) {
    asm volatile("mma.sync.aligned.m16n8k16.row.col.f32.f16.f16.f32 "
                 "{%0,%1,%2,%3}, {%4,%5,%6,%7}, {%8,%9}, {%0,%1,%2,%3};"
                 : "+f"(c0), "+f"(c1), "+f"(c2), "+f"(c3)
                 : "r"(a0), "r"(a1), "r"(a2), "r"(a3), "r"(b0), "r"(b1));
}
__device__ __forceinline__ void ldsm4(uint32_t& r0, uint32_t& r1, uint32_t& r2, uint32_t& r3,
                                      uint32_t addr) {
    asm volatile("ldmatrix.sync.aligned.m8n8.x4.shared.b16 {%0,%1,%2,%3}, [%4];"
                 : "=r"(r0), "=r"(r1), "=r"(r2), "=r"(r3) : "r"(addr));
}
__device__ __forceinline__ void split_hl(float x, __half& hi, __half& lo) {
    hi = __float2half_rn(x);
    lo = __float2half_rn((x - __half2float(hi)) * LOSCALE);
}

// ---------------- small kernels ----------------
__global__ void zero_counts_kernel() { if (threadIdx.x < E_) g_counts[threadIdx.x] = 0; }

__global__ void __launch_bounds__(256)
rmsnorm_hl_kernel(const float* __restrict__ X, const float* __restrict__ W) {
    int t = blockIdx.x, tid = threadIdx.x;
    float4 x = ((const float4*)(X + (size_t)t * D_))[tid];
    float ss = x.x*x.x + x.y*x.y + x.z*x.z + x.w*x.w;
    __shared__ float red[256];
    red[tid] = ss; __syncthreads();
    for (int s = 128; s > 0; s >>= 1) { if (tid < s) red[tid] += red[tid + s]; __syncthreads(); }
    float inv = rsqrtf(red[0] * (1.0f / 1024.0f) + 1e-6f);
    float4 w = ((const float4*)W)[tid];
    float y0 = x.x*inv*w.x, y1 = x.y*inv*w.y, y2 = x.z*inv*w.z, y3 = x.w*inv*w.w;
    __half h0,h1,h2,h3, l0,l1,l2,l3;
    split_hl(y0,h0,l0); split_hl(y1,h1,l1); split_hl(y2,h2,l2); split_hl(y3,h3,l3);
    __half2 hh0 = __halves2half2(h0,h1), hh1 = __halves2half2(h2,h3);
    __half2 ll0 = __halves2half2(l0,l1), ll1 = __halves2half2(l2,l3);
    uint2 ho, lo;
    ho.x = *(uint32_t*)&hh0; ho.y = *(uint32_t*)&hh1;
    lo.x = *(uint32_t*)&ll0; lo.y = *(uint32_t*)&ll1;
    ((uint2*)(g_xnh + (size_t)t * D_))[tid] = ho;
    ((uint2*)(g_xnl + (size_t)t * D_))[tid] = lo;
}

__global__ void __launch_bounds__(256)
rmsnorm_kernel(const float* __restrict__ X, const float* __restrict__ W, float* __restrict__ Yo) {
    int t = blockIdx.x, tid = threadIdx.x;
    float4 x = ((const float4*)(X + (size_t)t * D_))[tid];
    float ss = x.x*x.x + x.y*x.y + x.z*x.z + x.w*x.w;
    __shared__ float red[256];
    red[tid] = ss; __syncthreads();
    for (int s = 128; s > 0; s >>= 1) { if (tid < s) red[tid] += red[tid + s]; __syncthreads(); }
    float inv = rsqrtf(red[0] * (1.0f / 1024.0f) + 1e-6f);
    float4 w = ((const float4*)W)[tid];
    float4 y;
    y.x = x.x*inv*w.x; y.y = x.y*inv*w.y; y.z = x.z*inv*w.z; y.w = x.w*inv*w.w;
    ((float4*)(Yo + (size_t)t * D_))[tid] = y;
}

// fused 4-weight hi/lo decomposition (z selects weight)
__global__ void __launch_bounds__(256)
decomp_w4_kernel(const float* __restrict__ s0, const float* __restrict__ s1,
                 const float* __restrict__ s2, const float* __restrict__ s3) {
    int z = blockIdx.z;
    const float* src = z == 0 ? s0 : z == 1 ? s1 : z == 2 ? s2 : s3;
    size_t i = (size_t)blockIdx.x * 256 + threadIdx.x;
    __half* dh = g_wdh + (size_t)z * D_ * D_;
    __half* dl = g_wdl + (size_t)z * D_ * D_;
    float4 v = ((const float4*)src)[i];
    __half h0,h1,h2,h3, l0,l1,l2,l3;
    split_hl(v.x,h0,l0); split_hl(v.y,h1,l1); split_hl(v.z,h2,l2); split_hl(v.w,h3,l3);
    __half2 hh0 = __halves2half2(h0,h1), hh1 = __halves2half2(h2,h3);
    __half2 ll0 = __halves2half2(l0,l1), ll1 = __halves2half2(l2,l3);
    uint2 ho, lo;
    ho.x = *(uint32_t*)&hh0; ho.y = *(uint32_t*)&hh1;
    lo.x = *(uint32_t*)&ll0; lo.y = *(uint32_t*)&ll1;
    ((uint2*)dh)[i] = ho;
    ((uint2*)dl)[i] = lo;
}

// fused 3-weight fp32->fp16 copy (z selects weight)
__global__ void __launch_bounds__(256)
round_copy3_kernel(const float* __restrict__ s1, const float* __restrict__ s2,
                   const float* __restrict__ s3) {
    int z = blockIdx.z;
    const float* src = z == 0 ? s1 : z == 1 ? s2 : s3;
    __half* dst = z == 0 ? g_w1h : z == 1 ? g_w2h : g_w3h;
    size_t i = (size_t)blockIdx.x * 256 + threadIdx.x;
    float4 v = ((const float4*)src)[i];
    __half2 h0 = __floats2half2_rn(v.x, v.y);
    __half2 h1 = __floats2half2_rn(v.z, v.w);
    uint2 o; o.x = *(uint32_t*)&h0; o.y = *(uint32_t*)&h1;
    ((uint2*)dst)[i] = o;
}

__global__ void __launch_bounds__(256)
gather_h_kernel(const float* __restrict__ Hn) {
    int i = blockIdx.x * 256 + threadIdx.x;
    int slot = i >> 8, d4 = i & 255;
    int t = g_slot_token[slot];
    float4 v = ((const float4*)(Hn + (size_t)t * D_))[d4];
    __half2 h0 = __floats2half2_rn(v.x, v.y);
    __half2 h1 = __floats2half2_rn(v.z, v.w);
    uint2 o; o.x = *(uint32_t*)&h0; o.y = *(uint32_t*)&h1;
    ((uint2*)(g_Ag + (size_t)slot * D_))[d4] = o;
}

// ================= dense 2xFP16 compensated GEMM =================
#define KCH 64
#define STRDH 72
#define OPB (128*STRDH*2)
#define DX_ST (4*OPB)                  // Ah|Al|Bh|Bl = 73728
#define DX_SM (3*DX_ST)                // 221184 (3-stage)

template<bool ADDRES>
__global__ void __launch_bounds__(256, 1)
dense3x(const __half* __restrict__ Ah, const __half* __restrict__ Al,
        const __half* __restrict__ Bh, const __half* __restrict__ Bl,
        int bzoff, float* __restrict__ C, size_t czstride,
        const float* __restrict__ Res) {
    int z = blockIdx.z;
    int m0b = blockIdx.y * 128, n0b = blockIdx.x * 128;
    const __half* Ahrow = Ah + (size_t)m0b * D_;
    const __half* Alrow = Al + (size_t)m0b * D_;
    const __half* Bhrow = Bh + ((size_t)(bzoff + z) * 1024 + n0b) * D_;
    const __half* Blrow = Bl + ((size_t)(bzoff + z) * 1024 + n0b) * D_;
    float* Cz = C + (size_t)z * czstride;

    extern __shared__ __half smh[];
    uint32_t sm0 = smem_u32(smh);

    int tid = threadIdx.x;
    int wid = tid >> 5, lane = tid & 31;
    int wm = wid >> 2, wn = wid & 3;
    int g = lane >> 2, qd = lane & 3;

    int arow = (lane & 7) + ((lane >> 3) & 1) * 8;
    int acolh = ((lane >> 4) & 1) * 8;
    // B x4: lanes 0-7:(n,k0) 8-15:(n,k8) 16-23:(n+8,k0) 24-31:(n+8,k8)
    int b4row = (lane & 7) + ((lane >> 4) & 1) * 8;
    int b4colh = ((lane >> 3) & 1) * 8;
    uint32_t offAh[4], offBh4[2];
    #pragma unroll
    for (int mi = 0; mi < 4; mi++)
        offAh[mi] = ((wm * 64 + mi * 16 + arow) * STRDH + acolh) * 2;
    #pragma unroll
    for (int p = 0; p < 2; p++)
        offBh4[p] = 2 * OPB + ((wn * 32 + p * 16 + b4row) * STRDH + b4colh) * 2;

    float cm[4][4][4], cc[4][4][4];
    #pragma unroll
    for (int mi = 0; mi < 4; mi++)
        #pragma unroll
        for (int ni = 0; ni < 4; ni++)
            #pragma unroll
            for (int r = 0; r < 4; r++) { cm[mi][ni][r] = 0.f; cc[mi][ni][r] = 0.f; }

    int lrow[4], lseg[4];
    #pragma unroll
    for (int j = 0; j < 4; j++) {
        int idx = tid + j * 256;
        lrow[j] = idx >> 3;
        lseg[j] = idx & 7;
    }

    const int NC = D_ / KCH;   // 16

    #pragma unroll
    for (int pc = 0; pc < 2; pc++) {
        uint32_t sb = sm0 + pc * DX_ST;
        #pragma unroll
        for (int j = 0; j < 4; j++) {
            uint32_t d = lrow[j] * (STRDH * 2) + lseg[j] * 16;
            size_t go = (size_t)lrow[j] * D_ + pc * KCH + lseg[j] * 8;
            cp16(sb + d,           Ahrow + go);
            cp16(sb + OPB + d,     Alrow + go);
            cp16(sb + 2 * OPB + d, Bhrow + go);
            cp16(sb + 3 * OPB + d, Blrow + go);
        }
        CP_COMMIT();
    }

    for (int c = 0; c < NC; c++) {
        CP_WAIT1();
        __syncthreads();
        if (c + 2 < NC) {
            uint32_t sb = sm0 + ((c + 2) % 3) * DX_ST;
            #pragma unroll
            for (int j = 0; j < 4; j++) {
                uint32_t d = lrow[j] * (STRDH * 2) + lseg[j] * 16;
                size_t go = (size_t)lrow[j] * D_ + (c + 2) * KCH + lseg[j] * 8;
                cp16(sb + d,           Ahrow + go);
                cp16(sb + OPB + d,     Alrow + go);
                cp16(sb + 2 * OPB + d, Bhrow + go);
                cp16(sb + 3 * OPB + d, Blrow + go);
            }
        }
        CP_COMMIT();
        uint32_t sb = sm0 + (c % 3) * DX_ST;
        #pragma unroll
        for (int ks = 0; ks < KCH / 16; ks++) {
            uint32_t ko = sb + ks * 32;
            uint32_t ah[4][4], al[4][4];
            #pragma unroll
            for (int mi = 0; mi < 4; mi++) {
                ldsm4(ah[mi][0], ah[mi][1], ah[mi][2], ah[mi][3], offAh[mi] + ko);
                ldsm4(al[mi][0], al[mi][1], al[mi][2], al[mi][3], offAh[mi] + OPB + ko);
            }
            uint32_t bh[4][2], bl[4][2];
            #pragma unroll
            for (int p = 0; p < 2; p++) {
                ldsm4(bh[2*p][0], bh[2*p][1], bh[2*p+1][0], bh[2*p+1][1], offBh4[p] + ko);
                ldsm4(bl[2*p][0], bl[2*p][1], bl[2*p+1][0], bl[2*p+1][1], offBh4[p] + OPB + ko);
            }
            #pragma unroll
            for (int mi = 0; mi < 4; mi++)
                #pragma unroll
                for (int ni = 0; ni < 4; ni++) {
                    mma_f16(cm[mi][ni][0], cm[mi][ni][1], cm[mi][ni][2], cm[mi][ni][3],
                            ah[mi][0], ah[mi][1], ah[mi][2], ah[mi][3], bh[ni][0], bh[ni][1]);
                    mma_f16(cc[mi][ni][0], cc[mi][ni][1], cc[mi][ni][2], cc[mi][ni][3],
                            ah[mi][0], ah[mi][1], ah[mi][2], ah[mi][3], bl[ni][0], bl[ni][1]);
                    mma_f16(cc[mi][ni][0], cc[mi][ni][1], cc[mi][ni][2], cc[mi][ni][3],
                            al[mi][0], al[mi][1], al[mi][2], al[mi][3], bh[ni][0], bh[ni][1]);
                }
        }
        __syncthreads();
    }

    #pragma unroll
    for (int mi = 0; mi < 4; mi++) {
        int mr0 = m0b + wm * 64 + mi * 16 + g;
        #pragma unroll
        for (int ni = 0; ni < 4; ni++) {
            int col = n0b + wn * 32 + ni * 8 + qd * 2;
            float2 v0, v1;
            v0.x = cm[mi][ni][0] + cc[mi][ni][0] * INVLOSCALE;
            v0.y = cm[mi][ni][1] + cc[mi][ni][1] * INVLOSCALE;
            v1.x = cm[mi][ni][2] + cc[mi][ni][2] * INVLOSCALE;
            v1.y = cm[mi][ni][3] + cc[mi][ni][3] * INVLOSCALE;
            if (ADDRES) {
                float2 r0 = *(const float2*)(Res + (size_t)mr0 * D_ + col);
                float2 r1 = *(const float2*)(Res + (size_t)(mr0 + 8) * D_ + col);
                v0.x += r0.x; v0.y += r0.y; v1.x += r1.x; v1.y += r1.y;
            }
            *(float2*)(Cz + (size_t)mr0 * D_ + col) = v0;
            *(float2*)(Cz + (size_t)(mr0 + 8) * D_ + col) = v1;
        }
    }
}

// ---------------- RoPE ----------------
__global__ void rope_kernel(float* __restrict__ qh, float* __restrict__ kh,
                            const float* __restrict__ cosb, const float* __restrict__ sinb) {
    int idx = blockIdx.x * blockDim.x + threadIdx.x;
    if (idx >= T_ * H_ * 32) return;
    int p = idx & 31, h = (idx >> 5) & (H_ - 1), t = idx >> 9, s = t & (S_ - 1);
    float c = cosb[s * 32 + p], sn = sinb[s * 32 + p];
    size_t off = (size_t)t * D_ + h * HD_ + 2 * p;
    float2 qv = *(float2*)(qh + off);
    float2 kv = *(float2*)(kh + off);
    float2 qo, ko;
    qo.x = (qv.x * c - qv.y * sn) * 0.125f;
    qo.y = (qv.x * sn + qv.y * c) * 0.125f;
    ko.x = kv.x * c - kv.y * sn;
    ko.y = kv.x * sn + kv.y * c;
    *(float2*)(qh + off) = qo;
    *(float2*)(kh + off) = ko;
}

// ---------------- attention (fp32; emits hi/lo fp16) ----------------
__global__ void __launch_bounds__(128)
attn_kernel(const float* __restrict__ Q, const float* __restrict__ Kh,
            const float* __restrict__ Vh) {
    int b = blockIdx.z, h = blockIdx.y, qt = blockIdx.x;
    int tid = threadIdx.x;
    int r = qt * 128 + tid;
    __shared__ float4 Ks[64][16];
    __shared__ float4 Vs[64][16];
    size_t qbase = ((size_t)(b * S_ + r)) * D_ + h * HD_;
    float4 q4[16];
    #pragma unroll
    for (int i = 0; i < 16; i++) q4[i] = *(const float4*)(Q + qbase + i * 4);
    float4 o4[16];
    #pragma unroll
    for (int i = 0; i < 16; i++) o4[i] = make_float4(0.f, 0.f, 0.f, 0.f);
    float mrow = -1e30f, l = 0.f;
    int ntiles = qt * 2 + 2;
    for (int kt = 0; kt < ntiles; kt++) {
        int k0 = kt * 64;
        int j = tid >> 1, half = (tid & 1) * 8;
        size_t kb = ((size_t)(b * S_ + k0 + j)) * D_ + h * HD_ + half * 4;
        #pragma unroll
        for (int i = 0; i < 8; i++) {
            Ks[j][half + i] = *(const float4*)(Kh + kb + i * 4);
            Vs[j][half + i] = *(const float4*)(Vh + kb + i * 4);
        }
        __syncthreads();
        int jmax = r - k0 + 1;
        if (jmax > 64) jmax = 64;
        for (int jj = 0; jj < jmax; jj++) {
            float s0 = 0.f, s1 = 0.f, s2 = 0.f, s3 = 0.f;
            #pragma unroll
            for (int i = 0; i < 16; i += 4) {
                float4 k0v = Ks[jj][i],   k1v = Ks[jj][i+1];
                float4 k2v = Ks[jj][i+2], k3v = Ks[jj][i+3];
                s0 = fmaf(q4[i].x,   k0v.x, fmaf(q4[i].y,   k0v.y, fmaf(q4[i].z,   k0v.z, fmaf(q4[i].w,   k0v.w, s0))));
                s1 = fmaf(q4[i+1].x, k1v.x, fmaf(q4[i+1].y, k1v.y, fmaf(q4[i+1].z, k1v.z, fmaf(q4[i+1].w, k1v.w, s1))));
                s2 = fmaf(q4[i+2].x, k2v.x, fmaf(q4[i+2].y, k2v.y, fmaf(q4[i+2].z, k2v.z, fmaf(q4[i+2].w, k2v.w, s2))));
                s3 = fmaf(q4[i+3].x, k3v.x, fmaf(q4[i+3].y, k3v.y, fmaf(q4[i+3].z, k3v.z, fmaf(q4[i+3].w, k3v.w, s3))));
            }
            float s = (s0 + s1) + (s2 + s3);
            if (s <= mrow) {
                float p = __expf(s - mrow);
                l += p;
                #pragma unroll
                for (int i = 0; i < 16; i++) {
                    float4 vv = Vs[jj][i];
                    o4[i].x = fmaf(p, vv.x, o4[i].x); o4[i].y = fmaf(p, vv.y, o4[i].y);
                    o4[i].z = fmaf(p, vv.z, o4[i].z); o4[i].w = fmaf(p, vv.w, o4[i].w);
                }
            } else {
                float esc = __expf(mrow - s);
                mrow = s;
                l = fmaf(l, esc, 1.f);
                #pragma unroll
                for (int i = 0; i < 16; i++) {
                    float4 vv = Vs[jj][i];
                    o4[i].x = fmaf(o4[i].x, esc, vv.x); o4[i].y = fmaf(o4[i].y, esc, vv.y);
                    o4[i].z = fmaf(o4[i].z, esc, vv.z); o4[i].w = fmaf(o4[i].w, esc, vv.w);
                }
            }
        }
        __syncthreads();
    }
    float inv = 1.f / l;
    #pragma unroll
    for (int i = 0; i < 16; i++) {
        float v0 = o4[i].x * inv, v1 = o4[i].y * inv, v2 = o4[i].z * inv, v3 = o4[i].w * inv;
        __half h0,h1,h2,h3, l0,l1,l2,l3;
        split_hl(v0,h0,l0); split_hl(v1,h1,l1); split_hl(v2,h2,l2); split_hl(v3,h3,l3);
        __half2 hh0 = __halves2half2(h0,h1), hh1 = __halves2half2(h2,h3);
        __half2 ll0 = __halves2half2(l0,l1), ll1 = __halves2half2(l2,l3);
        uint2 ho, lo;
        ho.x = *(uint32_t*)&hh0; ho.y = *(uint32_t*)&hh1;
        lo.x = *(uint32_t*)&ll0; lo.y = *(uint32_t*)&ll1;
        *(uint2*)(g_aih + qbase + i * 4) = ho;
        *(uint2*)(g_ail + qbase + i * 4) = lo;
    }
}

// ---------------- router / scan / assign ----------------
__global__ void __launch_bounds__(256)
router_kernel(const float* __restrict__ Hn, const float* __restrict__ RW,
              const float* __restrict__ RB) {
    int t = blockIdx.x;
    int w = threadIdx.x >> 5, lane = threadIdx.x & 31;
    const float* x = Hn + (size_t)t * D_;
    const float* rw = RW + (size_t)w * D_;
    float acc = 0.f;
    for (int d = lane * 4; d < D_; d += 128) {
        float4 xv = *(const float4*)(x + d);
        float4 wv = *(const float4*)(rw + d);
        acc += xv.x*wv.x + xv.y*wv.y + xv.z*wv.z + xv.w*wv.w;
    }
    #pragma unroll
    for (int o = 16; o; o >>= 1) acc += __shfl_xor_sync(0xffffffffu, acc, o);
    __shared__ float lg[E_];
    if (lane == 0) lg[w] = acc + RB[w];
    __syncthreads();
    if (threadIdx.x == 0) {
        float v0 = -1e30f, v1 = -1e30f; int i0 = 0, i1 = 0;
        #pragma unroll
        for (int e = 0; e < E_; e++) {
            float v = lg[e];
            if (v > v0) { v1 = v0; i1 = i0; v0 = v; i0 = e; }
            else if (v > v1) { v1 = v; i1 = e; }
        }
        float e1 = expf(v1 - v0);
        float inv = 1.f / (1.f + e1);
        g_topi[t*2] = i0; g_topi[t*2+1] = i1;
        g_gate[t*2] = inv; g_gate[t*2+1] = e1 * inv;
        atomicAdd(&g_counts[i0], 1);
        atomicAdd(&g_counts[i1], 1);
    }
}

__global__ void scan_kernel() {
    if (threadIdx.x == 0) {
        int o = 0;
        for (int e = 0; e < E_; e++) { g_offs[e] = o; g_cursor[e] = o; o += g_counts[e]; }
    }
}

__global__ void assign_kernel() {
    int t = blockIdx.x * blockDim.x + threadIdx.x;
    if (t >= T_) return;
    #pragma unroll
    for (int j = 0; j < 2; j++) {
        int e = g_topi[t*2+j];
        int slot = atomicAdd(&g_cursor[e], 1);
        g_slot_token[slot] = t;
        g_token_slot[t*2+j] = slot;
    }
}

// ================= MoE fp16 mma.sync GEMMs =================
#define W13_ST (3*OPB)                 // 55296
#define W13_SM (3*W13_ST)              // 165888 (3-stage, 1 CTA/SM)
#define W2_ST  (2*OPB)                 // 36864
#define W2_SM  (3*W2_ST)               // 110592 (3-stage, 2 CTA/SM)

__global__ void __launch_bounds__(256, 1)
moe_w13(const __half* __restrict__ A, const __half* __restrict__ W1,
        const __half* __restrict__ W3, __half* __restrict__ G) {
    int e = blockIdx.z;
    int cnt = g_counts[e];
    int m0b = blockIdx.y * 128;
    if (m0b >= cnt) return;
    int base = g_offs[e];
    int n0b = blockIdx.x * 128;
    const __half* Arow  = A  + (size_t)(base + m0b) * D_;
    const __half* B1row = W1 + (size_t)e * F_ * D_ + (size_t)n0b * D_;
    const __half* B3row = W3 + (size_t)e * F_ * D_ + (size_t)n0b * D_;

    extern __shared__ __half smh[];
    uint32_t sm0 = smem_u32(smh);

    int tid = threadIdx.x;
    int wid = tid >> 5, lane = tid & 31;
    int wm = wid >> 2, wn = wid & 3;
    int g = lane >> 2, qd = lane & 3;

    int arow = (lane & 7) + ((lane >> 3) & 1) * 8;
    int acolh = ((lane >> 4) & 1) * 8;
    int b4row = (lane & 7) + ((lane >> 4) & 1) * 8;
    int b4colh = ((lane >> 3) & 1) * 8;
    uint32_t offA[4], offB14[2], offB34[2];
    #pragma unroll
    for (int mi = 0; mi < 4; mi++)
        offA[mi] = ((wm * 64 + mi * 16 + arow) * STRDH + acolh) * 2;
    #pragma unroll
    for (int p = 0; p < 2; p++) {
        uint32_t o = ((wn * 32 + p * 16 + b4row) * STRDH + b4colh) * 2;
        offB14[p] = OPB + o;
        offB34[p] = 2 * OPB + o;
    }

    float c1[4][4][4], c3[4][4][4];
    #pragma unroll
    for (int mi = 0; mi < 4; mi++)
        #pragma unroll
        for (int ni = 0; ni < 4; ni++)
            #pragma unroll
            for (int r = 0; r < 4; r++) { c1[mi][ni][r] = 0.f; c3[mi][ni][r] = 0.f; }

    int lrow[4], lseg[4];
    #pragma unroll
    for (int j = 0; j < 4; j++) {
        int idx = tid + j * 256;
        lrow[j] = idx >> 3;
        lseg[j] = idx & 7;
    }

    const int NC = D_ / KCH;   // 16

    #pragma unroll
    for (int pc = 0; pc < 2; pc++) {
        uint32_t sb = sm0 + pc * W13_ST;
        #pragma unroll
        for (int j = 0; j < 4; j++) {
            uint32_t d = lrow[j] * (STRDH * 2) + lseg[j] * 16;
            size_t go = (size_t)lrow[j] * D_ + pc * KCH + lseg[j] * 8;
            cp16(sb + d, Arow + go);
            cp16(sb + OPB + d, B1row + go);
            cp16(sb + 2 * OPB + d, B3row + go);
        }
        CP_COMMIT();
    }

    for (int c = 0; c < NC; c++) {
        CP_WAIT1();
        __syncthreads();
        if (c + 2 < NC) {
            uint32_t sb = sm0 + ((c + 2) % 3) * W13_ST;
            #pragma unroll
            for (int j = 0; j < 4; j++) {
                uint32_t d = lrow[j] * (STRDH * 2) + lseg[j] * 16;
                size_t go = (size_t)lrow[j] * D_ + (c + 2) * KCH + lseg[j] * 8;
                cp16(sb + d, Arow + go);
                cp16(sb + OPB + d, B1row + go);
                cp16(sb + 2 * OPB + d, B3row + go);
            }
        }
        CP_COMMIT();
        uint32_t sb = sm0 + (c % 3) * W13_ST;
        #pragma unroll
        for (int ks = 0; ks < KCH / 16; ks++) {
            uint32_t ko = sb + ks * 32;
            uint32_t a[4][4];
            #pragma unroll
            for (int mi = 0; mi < 4; mi++)
                ldsm4(a[mi][0], a[mi][1], a[mi][2], a[mi][3], offA[mi] + ko);
            uint32_t b[4][2];
            #pragma unroll
            for (int p = 0; p < 2; p++)
                ldsm4(b[2*p][0], b[2*p][1], b[2*p+1][0], b[2*p+1][1], offB14[p] + ko);
            #pragma unroll
            for (int mi = 0; mi < 4; mi++)
                #pragma unroll
                for (int ni = 0; ni < 4; ni++)
                    mma_f16(c1[mi][ni][0], c1[mi][ni][1], c1[mi][ni][2], c1[mi][ni][3],
                            a[mi][0], a[mi][1], a[mi][2], a[mi][3], b[ni][0], b[ni][1]);
            #pragma unroll
            for (int p = 0; p < 2; p++)
                ldsm4(b[2*p][0], b[2*p][1], b[2*p+1][0], b[2*p+1][1], offB34[p] + ko);
            #pragma unroll
            for (int mi = 0; mi < 4; mi++)
                #pragma unroll
                for (int ni = 0; ni < 4; ni++)
                    mma_f16(c3[mi][ni][0], c3[mi][ni][1], c3[mi][ni][2], c3[mi][ni][3],
                            a[mi][0], a[mi][1], a[mi][2], a[mi][3], b[ni][0], b[ni][1]);
        }
        __syncthreads();
    }

    #pragma unroll
    for (int mi = 0; mi < 4; mi++) {
        int mr0 = m0b + wm * 64 + mi * 16 + g;
        #pragma unroll
        for (int ni = 0; ni < 4; ni++) {
            int col = n0b + wn * 32 + ni * 8 + qd * 2;
            if (mr0 < cnt) {
                float h1 = c1[mi][ni][0], h3 = c3[mi][ni][0];
                float vx = h1 / (1.f + __expf(-h1)) * h3;
                h1 = c1[mi][ni][1]; h3 = c3[mi][ni][1];
                float vy = h1 / (1.f + __expf(-h1)) * h3;
                *(__half2*)(G + (size_t)(base + mr0) * F_ + col) = __floats2half2_rn(vx, vy);
            }
            if (mr0 + 8 < cnt) {
                float h1 = c1[mi][ni][2], h3 = c3[mi][ni][2];
                float vx = h1 / (1.f + __expf(-h1)) * h3;
                h1 = c1[mi][ni][3]; h3 = c3[mi][ni][3];
                float vy = h1 / (1.f + __expf(-h1)) * h3;
                *(__half2*)(G + (size_t)(base + mr0 + 8) * F_ + col) = __floats2half2_rn(vx, vy);
            }
        }
    }
}

// Y = G @ w2^T. 3-stage, 2 CTAs/SM.
__global__ void __launch_bounds__(256, 2)
moe_w2(const __half* __restrict__ A, const __half* __restrict__ Bw, float* __restrict__ Y) {
    int e = blockIdx.z;
    int cnt = g_counts[e];
    int m0b = blockIdx.y * 128;
    if (m0b >= cnt) return;
    int base = g_offs[e];
    int n0b = blockIdx.x * 128;
    const __half* Arow = A  + (size_t)(base + m0b) * F_;
    const __half* Brow = Bw + (size_t)e * D_ * F_ + (size_t)n0b * F_;

    extern __shared__ __half smh[];
    uint32_t sm0 = smem_u32(smh);

    int tid = threadIdx.x;
    int wid = tid >> 5, lane = tid & 31;
    int wm = wid >> 2, wn = wid & 3;
    int g = lane >> 2, qd = lane & 3;

    int arow = (lane & 7) + ((lane >> 3) & 1) * 8;
    int acolh = ((lane >> 4) & 1) * 8;
    int b4row = (lane & 7) + ((lane >> 4) & 1) * 8;
    int b4colh = ((lane >> 3) & 1) * 8;
    uint32_t offA[4], offB4[2];
    #pragma unroll
    for (int mi = 0; mi < 4; mi++)
        offA[mi] = ((wm * 64 + mi * 16 + arow) * STRDH + acolh) * 2;
    #pragma unroll
    for (int p = 0; p < 2; p++)
        offB4[p] = OPB + ((wn * 32 + p * 16 + b4row) * STRDH + b4colh) * 2;

    float c[4][4][4];
    #pragma unroll
    for (int mi = 0; mi < 4; mi++)
        #pragma unroll
        for (int ni = 0; ni < 4; ni++)
            #pragma unroll
            for (int r = 0; r < 4; r++) c[mi][ni][r] = 0.f;

    int lrow[4], lseg[4];
    #pragma unroll
    for (int j = 0; j < 4; j++) {
        int idx = tid + j * 256;
        lrow[j] = idx >> 3;
        lseg[j] = idx & 7;
    }

    const int NC = F_ / KCH;   // 64

    #pragma unroll
    for (int pc = 0; pc < 2; pc++) {
        uint32_t sb = sm0 + pc * W2_ST;
        #pragma unroll
        for (int j = 0; j < 4; j++) {
            uint32_t d = lrow[j] * (STRDH * 2) + lseg[j] * 16;
            size_t go = (size_t)lrow[j] * F_ + pc * KCH + lseg[j] * 8;
            cp16(sb + d, Arow + go);
            cp16(sb + OPB + d, Brow + go);
        }
        CP_COMMIT();
    }

    for (int cix = 0; cix < NC; cix++) {
        CP_WAIT1();
        __syncthreads();
        if (cix + 2 < NC) {
            uint32_t sb = sm0 + ((cix + 2) % 3) * W2_ST;
            #pragma unroll
            for (int j = 0; j < 4; j++) {
                uint32_t d = lrow[j] * (STRDH * 2) + lseg[j] * 16;
                size_t go = (size_t)lrow[j] * F_ + (cix + 2) * KCH + lseg[j] * 8;
                cp16(sb + d, Arow + go);
                cp16(sb + OPB + d, Brow + go);
            }
        }
        CP_COMMIT();
        uint32_t sb = sm0 + (cix % 3) * W2_ST;
        #pragma unroll
        for (int ks = 0; ks < KCH / 16; ks++) {
            uint32_t ko = sb + ks * 32;
            uint32_t a[4][4];
            #pragma unroll
            for (int mi = 0; mi < 4; mi++)
                ldsm4(a[mi][0], a[mi][1], a[mi][2], a[mi][3], offA[mi] + ko);
            uint32_t b[4][2];
            #pragma unroll
            for (int p = 0; p < 2; p++)
                ldsm4(b[2*p][0], b[2*p][1], b[2*p+1][0], b[2*p+1][1], offB4[p] + ko);
            #pragma unroll
            for (int mi = 0; mi < 4; mi++)
                #pragma unroll
                for (int ni = 0; ni < 4; ni++)
                    mma_f16(c[mi][ni][0], c[mi][ni][1], c[mi][ni][2], c[mi][ni][3],
                            a[mi][0], a[mi][1], a[mi][2], a[mi][3], b[ni][0], b[ni][1]);
        }
        __syncthreads();
    }

    #pragma unroll
    for (int mi = 0; mi < 4; mi++) {
        int mr0 = m0b + wm * 64 + mi * 16 + g;
        #pragma unroll
        for (int ni = 0; ni < 4; ni++) {
            int col = n0b + wn * 32 + ni * 8 + qd * 2;
            if (mr0 < cnt) {
                float2 v; v.x = c[mi][ni][0]; v.y = c[mi][ni][1];
                *(float2*)(Y + (size_t)(base + mr0) * D_ + col) = v;
            }
            if (mr0 + 8 < cnt) {
                float2 v; v.x = c[mi][ni][2]; v.y = c[mi][ni][3];
                *(float2*)(Y + (size_t)(base + mr0 + 8) * D_ + col) = v;
            }
        }
    }
}

// ---------------- combine ----------------
__global__ void combine_kernel(const float* __restrict__ Hres, float* __restrict__ Out) {
    int i = blockIdx.x * 256 + threadIdx.x;
    int t = i >> 8, d4 = i & 255;
    float g0 = g_gate[t*2], g1 = g_gate[t*2+1];
    int s0 = g_token_slot[t*2], s1 = g_token_slot[t*2+1];
    float4 hv = ((const float4*)(Hres + (size_t)t * D_))[d4];
    float4 y0 = ((const float4*)(g_Y + (size_t)s0 * D_))[d4];
    float4 y1 = ((const float4*)(g_Y + (size_t)s1 * D_))[d4];
    float4 o;
    o.x = hv.x + g0*y0.x + g1*y1.x;
    o.y = hv.y + g0*y0.y + g1*y1.y;
    o.z = hv.z + g0*y0.z + g1*y1.z;
    o.w = hv.w + g0*y0.w + g1*y1.w;
    ((float4*)Out)[i] = o;
}

// ---------------- host ----------------
extern "C" void kernel_launch(void* const* d_in, const int* in_sizes, int n_in,
                              void* d_out, int out_size) {
    const float* q    = (const float*)d_in[0];
    const float* fcos = (const float*)d_in[3];
    const float* fsin = (const float*)d_in[4];
    const float* attw = (const float*)d_in[5];
    const float* ffnw = (const float*)d_in[6];
    const float* wq   = (const float*)d_in[7];
    const float* wk   = (const float*)d_in[8];
    const float* wv   = (const float*)d_in[9];
    const float* wo   = (const float*)d_in[10];
    const float* rw   = (const float*)d_in[11];
    const float* rb   = (const float*)d_in[12];
    const float* w1   = (const float*)d_in[13];
    const float* w2   = (const float*)d_in[14];
    const float* w3   = (const float*)d_in[15];
    float* out = (float*)d_out;

    float *qkv, *hbuf, *hn, *Y;
    __half *xnh, *xnl, *aih, *ail, *wdh, *wdl, *Ag, *G, *w1h, *w2h, *w3h;
    cudaGetSymbolAddress((void**)&xnh,  g_xnh);
    cudaGetSymbolAddress((void**)&xnl,  g_xnl);
    cudaGetSymbolAddress((void**)&qkv,  g_qkv);
    cudaGetSymbolAddress((void**)&aih,  g_aih);
    cudaGetSymbolAddress((void**)&ail,  g_ail);
    cudaGetSymbolAddress((void**)&hbuf, g_h);
    cudaGetSymbolAddress((void**)&hn,   g_hn);
    cudaGetSymbolAddress((void**)&wdh,  g_wdh);
    cudaGetSymbolAddress((void**)&wdl,  g_wdl);
    cudaGetSymbolAddress((void**)&Ag,   g_Ag);
    cudaGetSymbolAddress((void**)&G,    g_G);
    cudaGetSymbolAddress((void**)&Y,    g_Y);
    cudaGetSymbolAddress((void**)&w1h,  g_w1h);
    cudaGetSymbolAddress((void**)&w2h,  g_w2h);
    cudaGetSymbolAddress((void**)&w3h,  g_w3h);

    cudaFuncSetAttribute(dense3x<false>, cudaFuncAttributeMaxDynamicSharedMemorySize, DX_SM);
    cudaFuncSetAttribute(dense3x<true>,  cudaFuncAttributeMaxDynamicSharedMemorySize, DX_SM);
    cudaFuncSetAttribute(moe_w13, cudaFuncAttributeMaxDynamicSharedMemorySize, W13_SM);
    cudaFuncSetAttribute(moe_w2,  cudaFuncAttributeMaxDynamicSharedMemorySize, W2_SM);

    decomp_w4_kernel<<<dim3(D_ * D_ / 4 / 256, 1, 4), 256>>>(wq, wk, wv, wo);
    round_copy3_kernel<<<dim3((int)((size_t)E_ * F_ * D_ / 4 / 256), 1, 3), 256>>>(w1, w2, w3);

    zero_counts_kernel<<<1, 32>>>();
    rmsnorm_hl_kernel<<<T_, 256>>>(q, attw);

    dense3x<false><<<dim3(8, 32, 3), 256, DX_SM>>>(xnh, xnl, wdh, wdl, 0,
                                                   qkv, (size_t)T_ * D_, nullptr);

    rope_kernel<<<(T_ * H_ * 32 + 255) / 256, 256>>>(qkv, qkv + (size_t)T_ * D_, fcos, fsin);
    attn_kernel<<<dim3(S_ / 128, H_, B_), 128>>>(qkv, qkv + (size_t)T_ * D_,
                                                 qkv + 2 * (size_t)T_ * D_);

    dense3x<true><<<dim3(8, 32, 1), 256, DX_SM>>>(aih, ail, wdh, wdl, 3,
                                                  hbuf, 0, q);

    rmsnorm_kernel<<<T_, 256>>>(hbuf, ffnw, hn);
    router_kernel<<<T_, 256>>>(hn, rw, rb);
    scan_kernel<<<1, 1>>>();
    assign_kernel<<<T_ / 256, 256>>>();
    gather_h_kernel<<<NSLOT * (D_ / 4) / 256, 256>>>(hn);

    moe_w13<<<dim3(F_ / 128, NSLOT / 128, E_), 256, W13_SM>>>(Ag, w1h, w3h, G);
    moe_w2 <<<dim3(D_ / 128, NSLOT / 128, E_), 256, W2_SM>>>(G, w2h, Y);

    combine_kernel<<<T_ * D_ / 4 / 256, 256>>>(hbuf, out);
}